// round 1
// baseline (speedup 1.0000x reference)
#include <cuda_runtime.h>
#include <math.h>
#include <stdint.h>
#include <stddef.h>

#define B_ 16
#define C_ 512
#define N_ 4096
#define NROWS (B_*C_)

// ---------------- scratch (device globals; no allocs allowed) ----------------
__device__ float g_qkv[(size_t)B_*3*C_*N_];   // (B, 3C, N)
__device__ float g_mqk[(size_t)B_*2*C_*N_];   // (B, 2C, N)
__device__ float g_qh [(size_t)B_*C_*N_];     // softmax(-relu(q*mq))
__device__ float g_kh [(size_t)B_*C_*N_];     // relu(k*mk)
__device__ float g_y  [(size_t)B_*C_*N_];     // attn @ v
__device__ float g_gp [(size_t)B_*C_*N_];     // gate pre-activation
__device__ float g_r  [(size_t)B_*C_*N_];     // Wr @ x + br

// ---------------------------------------------------------------------------
// Generic batched GEMM:  Y[b, m, n] = sum_k A[b, m, k] * X[b, k+chanOff, n]
//   A: row-major (lda), optional batch stride (0 => shared weights)
//   X: (B, *, N_) with batch stride xBatch, channel offset xChanOff
//   optional bias[m], optional accumulate into Y (addY)
// Tiles: BM=BN=128, BK=8, 256 threads, 8x8 per thread.
// grid: (N_/128, M/128, B)
// ---------------------------------------------------------------------------
__global__ void __launch_bounds__(256, 2) gemm_wx(
    const float* __restrict__ A, int lda, size_t aBatch,
    const float* __restrict__ X, size_t xBatch, int xChanOff,
    const float* __restrict__ bias,
    float* __restrict__ Y, size_t yBatch,
    int K, int addY)
{
    __shared__ float As[8][128];
    __shared__ float Bs[8][128];

    const int b  = blockIdx.z;
    const int m0 = blockIdx.y << 7;
    const int n0 = blockIdx.x << 7;
    const int tid = threadIdx.x;

    const int aRow = tid >> 1;          // 0..127
    const int aCol = (tid & 1) << 2;    // 0 or 4
    const int xRow = tid >> 5;          // 0..7
    const int xCol = (tid & 31) << 2;   // 0..124
    const int tx = tid & 15, ty = tid >> 4;

    const float* Aptr = A + (size_t)b*aBatch + (size_t)(m0 + aRow)*lda + aCol;
    const float* Xptr = X + (size_t)b*xBatch + ((size_t)xChanOff + xRow)*N_ + n0 + xCol;

    float acc[8][8];
    #pragma unroll
    for (int i = 0; i < 8; i++)
        #pragma unroll
        for (int j = 0; j < 8; j++) acc[i][j] = 0.f;

    for (int k0 = 0; k0 < K; k0 += 8) {
        float4 a4 = *(const float4*)(Aptr + k0);
        float4 x4 = *(const float4*)(Xptr + (size_t)k0 * N_);
        As[aCol+0][aRow] = a4.x;
        As[aCol+1][aRow] = a4.y;
        As[aCol+2][aRow] = a4.z;
        As[aCol+3][aRow] = a4.w;
        *(float4*)&Bs[xRow][xCol] = x4;
        __syncthreads();

        #pragma unroll
        for (int kk = 0; kk < 8; kk++) {
            float a[8], bb[8];
            *(float4*)(a)    = *(const float4*)&As[kk][ty*8];
            *(float4*)(a+4)  = *(const float4*)&As[kk][ty*8+4];
            *(float4*)(bb)   = *(const float4*)&Bs[kk][tx*8];
            *(float4*)(bb+4) = *(const float4*)&Bs[kk][tx*8+4];
            #pragma unroll
            for (int i = 0; i < 8; i++)
                #pragma unroll
                for (int j = 0; j < 8; j++)
                    acc[i][j] += a[i] * bb[j];
        }
        __syncthreads();
    }

    #pragma unroll
    for (int i = 0; i < 8; i++) {
        const int m = m0 + ty*8 + i;
        const float bi = bias ? bias[m] : 0.f;
        float* yp = Y + (size_t)b*yBatch + (size_t)m*N_ + n0 + tx*8;
        #pragma unroll
        for (int j = 0; j < 8; j++) {
            float val = acc[i][j] + bi;
            if (addY) val += yp[j];
            yp[j] = val;
        }
    }
}

// ---------------------------------------------------------------------------
// Scores GEMM (NT, K=N_=4096 contiguous in both operands):
//   S[b, c, d] = scale * sum_n Q[b,c,n] * Kh[b,d,n]
// grid: (C_/128, C_/128, B), 256 threads
// ---------------------------------------------------------------------------
__global__ void __launch_bounds__(256, 2) gemm_nt(
    const float* __restrict__ Q, const float* __restrict__ Kh,
    float* __restrict__ S, float scale)
{
    __shared__ float As[8][128];
    __shared__ float Bs[8][128];

    const int b  = blockIdx.z;
    const int m0 = blockIdx.y << 7;
    const int n0 = blockIdx.x << 7;
    const int tid = threadIdx.x;

    const int row = tid >> 1;
    const int col = (tid & 1) << 2;
    const int tx = tid & 15, ty = tid >> 4;

    const float* qp = Q  + (size_t)b*C_*N_ + (size_t)(m0 + row)*N_ + col;
    const float* kp = Kh + (size_t)b*C_*N_ + (size_t)(n0 + row)*N_ + col;

    float acc[8][8];
    #pragma unroll
    for (int i = 0; i < 8; i++)
        #pragma unroll
        for (int j = 0; j < 8; j++) acc[i][j] = 0.f;

    for (int k0 = 0; k0 < N_; k0 += 8) {
        float4 a4 = *(const float4*)(qp + k0);
        float4 b4 = *(const float4*)(kp + k0);
        As[col+0][row] = a4.x; As[col+1][row] = a4.y;
        As[col+2][row] = a4.z; As[col+3][row] = a4.w;
        Bs[col+0][row] = b4.x; Bs[col+1][row] = b4.y;
        Bs[col+2][row] = b4.z; Bs[col+3][row] = b4.w;
        __syncthreads();

        #pragma unroll
        for (int kk = 0; kk < 8; kk++) {
            float a[8], bb[8];
            *(float4*)(a)    = *(const float4*)&As[kk][ty*8];
            *(float4*)(a+4)  = *(const float4*)&As[kk][ty*8+4];
            *(float4*)(bb)   = *(const float4*)&Bs[kk][tx*8];
            *(float4*)(bb+4) = *(const float4*)&Bs[kk][tx*8+4];
            #pragma unroll
            for (int i = 0; i < 8; i++)
                #pragma unroll
                for (int j = 0; j < 8; j++)
                    acc[i][j] += a[i] * bb[j];
        }
        __syncthreads();
    }

    #pragma unroll
    for (int i = 0; i < 8; i++) {
        float* sp = S + (size_t)b*C_*C_ + (size_t)(m0 + ty*8 + i)*C_ + n0 + tx*8;
        #pragma unroll
        for (int j = 0; j < 8; j++)
            sp[j] = acc[i][j] * scale;
    }
}

// ---------------------------------------------------------------------------
// _q = softmax(-relu(q*mq), axis=n).  One block per (b,c) row, 256 threads.
// ---------------------------------------------------------------------------
__global__ void softmax_q(const float* __restrict__ qkv,
                          const float* __restrict__ mqk,
                          float* __restrict__ qh)
{
    __shared__ float red[8];
    __shared__ float bc;
    const int row = blockIdx.x;
    const int b = row >> 9, c = row & 511;
    const float* q  = qkv + ((size_t)b*1536 + c) * (size_t)N_;
    const float* mq = mqk + ((size_t)b*1024 + c) * (size_t)N_;
    float* o = qh + (size_t)row * N_;

    float v[16];
    float mx = -1e30f;
    #pragma unroll
    for (int i = 0; i < 16; i++) {
        int idx = threadIdx.x + (i << 8);
        float t = -fmaxf(q[idx] * mq[idx], 0.f);
        v[i] = t;
        mx = fmaxf(mx, t);
    }
    #pragma unroll
    for (int off = 16; off; off >>= 1)
        mx = fmaxf(mx, __shfl_xor_sync(0xffffffffu, mx, off));
    if ((threadIdx.x & 31) == 0) red[threadIdx.x >> 5] = mx;
    __syncthreads();
    if (threadIdx.x == 0) {
        float t = red[0];
        #pragma unroll
        for (int i = 1; i < 8; i++) t = fmaxf(t, red[i]);
        bc = t;
    }
    __syncthreads();
    mx = bc;

    float sm = 0.f;
    #pragma unroll
    for (int i = 0; i < 16; i++) {
        v[i] = __expf(v[i] - mx);
        sm += v[i];
    }
    #pragma unroll
    for (int off = 16; off; off >>= 1)
        sm += __shfl_xor_sync(0xffffffffu, sm, off);
    __syncthreads();   // protect red[] reuse
    if ((threadIdx.x & 31) == 0) red[threadIdx.x >> 5] = sm;
    __syncthreads();
    if (threadIdx.x == 0) {
        float t = 0.f;
        #pragma unroll
        for (int i = 0; i < 8; i++) t += red[i];
        bc = t;
    }
    __syncthreads();
    const float rinv = 1.f / bc;
    #pragma unroll
    for (int i = 0; i < 16; i++) {
        int idx = threadIdx.x + (i << 8);
        o[idx] = v[i] * rinv;
    }
}

// ---------------------------------------------------------------------------
// _k = relu(k*mk).  One block per (b,c) row, float4 path.
// ---------------------------------------------------------------------------
__global__ void relu_k(const float* __restrict__ qkv,
                       const float* __restrict__ mqk,
                       float* __restrict__ kh)
{
    const int row = blockIdx.x;
    const int b = row >> 9, c = row & 511;
    const float4* k4 = (const float4*)(qkv + ((size_t)b*1536 + 512 + c) * (size_t)N_);
    const float4* m4 = (const float4*)(mqk + ((size_t)b*1024 + 512 + c) * (size_t)N_);
    float4* o4 = (float4*)(kh + (size_t)row * N_);
    for (int i = threadIdx.x; i < N_/4; i += 256) {
        float4 a = k4[i], m = m4[i], r;
        r.x = fmaxf(a.x * m.x, 0.f);
        r.y = fmaxf(a.y * m.y, 0.f);
        r.z = fmaxf(a.z * m.z, 0.f);
        r.w = fmaxf(a.w * m.w, 0.f);
        o4[i] = r;
    }
}

// ---------------------------------------------------------------------------
// attn = softmax(scores, axis=d) in-place.  One block per (b,c) row, 128 thr.
// ---------------------------------------------------------------------------
__global__ void softmax_attn(float* __restrict__ S)
{
    __shared__ float red[4];
    __shared__ float bc;
    const int row = blockIdx.x;
    float* p = S + (size_t)row * 512;

    float v[4];
    float mx = -1e30f;
    #pragma unroll
    for (int i = 0; i < 4; i++) {
        int idx = threadIdx.x + (i << 7);
        v[i] = p[idx];
        mx = fmaxf(mx, v[i]);
    }
    #pragma unroll
    for (int off = 16; off; off >>= 1)
        mx = fmaxf(mx, __shfl_xor_sync(0xffffffffu, mx, off));
    if ((threadIdx.x & 31) == 0) red[threadIdx.x >> 5] = mx;
    __syncthreads();
    if (threadIdx.x == 0) {
        float t = fmaxf(fmaxf(red[0], red[1]), fmaxf(red[2], red[3]));
        bc = t;
    }
    __syncthreads();
    mx = bc;

    float sm = 0.f;
    #pragma unroll
    for (int i = 0; i < 4; i++) {
        v[i] = __expf(v[i] - mx);
        sm += v[i];
    }
    #pragma unroll
    for (int off = 16; off; off >>= 1)
        sm += __shfl_xor_sync(0xffffffffu, sm, off);
    __syncthreads();
    if ((threadIdx.x & 31) == 0) red[threadIdx.x >> 5] = sm;
    __syncthreads();
    if (threadIdx.x == 0) bc = red[0] + red[1] + red[2] + red[3];
    __syncthreads();
    const float rinv = 1.f / bc;
    #pragma unroll
    for (int i = 0; i < 4; i++) {
        int idx = threadIdx.x + (i << 7);
        p[idx] = v[i] * rinv;
    }
}

// ---------------------------------------------------------------------------
// out = g*r + (1-g)*y,  g = sigmoid(gpre).  One block per (b,c) row.
// ---------------------------------------------------------------------------
__global__ void fuse_out(const float* __restrict__ gp,
                         const float* __restrict__ r,
                         const float* __restrict__ y,
                         float* __restrict__ out)
{
    const size_t row = blockIdx.x;
    const float4* G = (const float4*)(gp  + row * N_);
    const float4* R = (const float4*)(r   + row * N_);
    const float4* Y = (const float4*)(y   + row * N_);
    float4* O = (float4*)(out + row * N_);
    for (int i = threadIdx.x; i < N_/4; i += 256) {
        float4 g4 = G[i], r4 = R[i], y4 = Y[i], o;
        float gx = 1.f / (1.f + __expf(-g4.x));
        float gy = 1.f / (1.f + __expf(-g4.y));
        float gz = 1.f / (1.f + __expf(-g4.z));
        float gw = 1.f / (1.f + __expf(-g4.w));
        o.x = y4.x + gx * (r4.x - y4.x);
        o.y = y4.y + gy * (r4.y - y4.y);
        o.z = y4.z + gz * (r4.z - y4.z);
        o.w = y4.w + gw * (r4.w - y4.w);
        O[i] = o;
    }
}

// ---------------------------------------------------------------------------
extern "C" void kernel_launch(void* const* d_in, const int* in_sizes, int n_in,
                              void* d_out, int out_size)
{
    const float* x    = (const float*)d_in[0];
    const float* Wqkv = (const float*)d_in[1];
    const float* bqkv = (const float*)d_in[2];
    const float* Wm   = (const float*)d_in[3];
    const float* bm   = (const float*)d_in[4];
    const float* Wg   = (const float*)d_in[5];
    const float* bg   = (const float*)d_in[6];
    const float* Wr   = (const float*)d_in[7];
    const float* br   = (const float*)d_in[8];

    float* out  = (float*)d_out;                        // (B, C, H, W)
    float* attn = out + (size_t)B_ * C_ * N_;           // (B, C, C)

    float *p_qkv, *p_mqk, *p_qh, *p_kh, *p_y, *p_gp, *p_r;
    cudaGetSymbolAddress((void**)&p_qkv, g_qkv);
    cudaGetSymbolAddress((void**)&p_mqk, g_mqk);
    cudaGetSymbolAddress((void**)&p_qh,  g_qh);
    cudaGetSymbolAddress((void**)&p_kh,  g_kh);
    cudaGetSymbolAddress((void**)&p_y,   g_y);
    cudaGetSymbolAddress((void**)&p_gp,  g_gp);
    cudaGetSymbolAddress((void**)&p_r,   g_r);

    const size_t sBCN  = (size_t)C_  * N_;      // per-batch stride of (B,C,N)
    const size_t s3CN  = (size_t)3*C_ * N_;
    const size_t s2CN  = (size_t)2*C_ * N_;
    const dim3 blk(256);

    // 1) qkv = Wqkv @ x + bqkv           (B, 3C, N)
    gemm_wx<<<dim3(N_/128, 3*C_/128, B_), blk>>>(
        Wqkv, C_, 0, x, sBCN, 0, bqkv, p_qkv, s3CN, C_, 0);

    // 2) mqk = Wm @ v + bm               (B, 2C, N);  v = qkv[:, 2C:]
    gemm_wx<<<dim3(N_/128, 2*C_/128, B_), blk>>>(
        Wm, C_, 0, p_qkv, s3CN, 2*C_, bm, p_mqk, s2CN, C_, 0);

    // 3) _q = softmax(-relu(q*mq), axis=n)
    softmax_q<<<NROWS, 256>>>(p_qkv, p_mqk, p_qh);

    // 4) _k = relu(k*mk)
    relu_k<<<NROWS, 256>>>(p_qkv, p_mqk, p_kh);

    // 5) scores = _q @ _k^T / sqrt(C)  -> attn region of d_out
    gemm_nt<<<dim3(C_/128, C_/128, B_), blk>>>(
        p_qh, p_kh, attn, 1.0f / sqrtf((float)C_));

    // 6) attn = softmax(scores, axis=d)  (in-place)
    softmax_attn<<<NROWS, 128>>>(attn);

    // 7) y = attn @ v
    gemm_wx<<<dim3(N_/128, C_/128, B_), blk>>>(
        attn, C_, (size_t)C_*C_, p_qkv, s3CN, 2*C_, nullptr, p_y, sBCN, C_, 0);

    // 8) gpre = Wg[:, :C] @ y + bg
    gemm_wx<<<dim3(N_/128, C_/128, B_), blk>>>(
        Wg, 2*C_, 0, p_y, sBCN, 0, bg, p_gp, sBCN, C_, 0);

    // 9) gpre += Wg[:, C:] @ x
    gemm_wx<<<dim3(N_/128, C_/128, B_), blk>>>(
        Wg + C_, 2*C_, 0, x, sBCN, 0, nullptr, p_gp, sBCN, C_, 1);

    // 10) r = Wr @ x + br
    gemm_wx<<<dim3(N_/128, C_/128, B_), blk>>>(
        Wr, C_, 0, x, sBCN, 0, br, p_r, sBCN, C_, 0);

    // 11) out = sigmoid(gpre)*r + (1-sigmoid(gpre))*y
    fuse_out<<<NROWS, 256>>>(p_gp, p_r, p_y, out);
}

// round 3
// speedup vs baseline: 1.7643x; 1.7643x over previous
#include <cuda_runtime.h>
#include <cuda_bf16.h>
#include <math.h>
#include <stdint.h>
#include <stddef.h>

#define B_ 16
#define C_ 512
#define N_ 4096
#define NROWS (B_*C_)

// block tile
#define TM 128
#define TN 128
#define TKC 32          // K per chunk (bf16 elems)

// ---------------- scratch (device globals) ----------------
__device__ float g_qkv[(size_t)B_*3*C_*N_];
__device__ float g_mqk[(size_t)B_*2*C_*N_];
__device__ float g_kh [(size_t)B_*C_*N_];
__device__ float g_y  [(size_t)B_*C_*N_];
__device__ float g_gp [(size_t)B_*C_*N_];
__device__ __nv_bfloat16 g_qh_h[(size_t)B_*C_*N_];
__device__ __nv_bfloat16 g_qh_l[(size_t)B_*C_*N_];
__device__ __nv_bfloat16 g_at_h[(size_t)B_*C_*C_];
__device__ __nv_bfloat16 g_at_l[(size_t)B_*C_*C_];
__device__ __nv_bfloat16 g_wqkv_h[3*C_*C_], g_wqkv_l[3*C_*C_];
__device__ __nv_bfloat16 g_wm_h[2*C_*C_],   g_wm_l[2*C_*C_];
__device__ __nv_bfloat16 g_wg_h[C_*2*C_],   g_wg_l[C_*2*C_];
__device__ __nv_bfloat16 g_wr_h[C_*C_],     g_wr_l[C_*C_];

// ---------------- PTX helpers (portable, no sm_103a features) ----------------
__device__ __forceinline__ uint32_t smem_u32(const void* p){
    uint32_t a;
    asm("{ .reg .u64 t; cvta.to.shared.u64 t, %1; cvt.u32.u64 %0, t; }"
        : "=r"(a) : "l"(p));
    return a;
}
__device__ __forceinline__ void ldsm4(uint32_t* r, uint32_t addr){
    asm volatile("ldmatrix.sync.aligned.m8n8.x4.shared.b16 {%0,%1,%2,%3}, [%4];"
        : "=r"(r[0]), "=r"(r[1]), "=r"(r[2]), "=r"(r[3]) : "r"(addr));
}
__device__ __forceinline__ void ldsm2(uint32_t* r, uint32_t addr){
    asm volatile("ldmatrix.sync.aligned.m8n8.x2.shared.b16 {%0,%1}, [%2];"
        : "=r"(r[0]), "=r"(r[1]) : "r"(addr));
}
__device__ __forceinline__ void ldsm2t(uint32_t* r, uint32_t addr){
    asm volatile("ldmatrix.sync.aligned.m8n8.x2.trans.shared.b16 {%0,%1}, [%2];"
        : "=r"(r[0]), "=r"(r[1]) : "r"(addr));
}
__device__ __forceinline__ void mma16816(float* c, const uint32_t* a, const uint32_t* b){
    asm volatile(
        "mma.sync.aligned.m16n8k16.row.col.f32.bf16.bf16.f32 "
        "{%0,%1,%2,%3}, {%4,%5,%6,%7}, {%8,%9}, {%0,%1,%2,%3};"
        : "+f"(c[0]), "+f"(c[1]), "+f"(c[2]), "+f"(c[3])
        : "r"(a[0]), "r"(a[1]), "r"(a[2]), "r"(a[3]), "r"(b[0]), "r"(b[1]));
}
__device__ __forceinline__ uint32_t pack_bf2(float x, float y){
    __nv_bfloat162 p(__float2bfloat16_rn(x), __float2bfloat16_rn(y));
    return *(uint32_t*)&p;
}

// ---------------------------------------------------------------------------
// bf16 split-operand GEMM on mma.sync (HMMA path).
//   Y[b, m, n] = epi( scale * sum_k A[b,m,k] * B[k][n] + bias[m] )
// A: pre-split bf16 hi/lo, row-major lda, batch stride aBatch.
// B fp32:
//   transB=1: MN-major X[(k+off)][n] stride N_; rows >= K1 come from X2.
//   transB=0: K-major rows  X1[(n0+n)][k], stride N_ (NT GEMM).
// epiMode 1: out = Ey + sigmoid(Egp) * ((d+bias) - Ey)
// ---------------------------------------------------------------------------
__global__ void __launch_bounds__(256, 2) mma_gemm(
    const __nv_bfloat16* __restrict__ Ah, const __nv_bfloat16* __restrict__ Al,
    int lda, size_t aBatch,
    const float* __restrict__ X1, size_t x1B, int x1Off, int K1,
    const float* __restrict__ X2, size_t x2B, int x2Off,
    const float* __restrict__ bias, float scale,
    float* __restrict__ Y, size_t yB, int yStride,
    int K, int transB,
    const float* __restrict__ Egp, const float* __restrict__ Ey, int epiMode)
{
    // padded smem: A [128][40] (stride 80B), B-nt [128][40], B-trans [32][136] (stride 272B)
    __shared__ __align__(16) __nv_bfloat16 sAh[128][40];
    __shared__ __align__(16) __nv_bfloat16 sAl[128][40];
    __shared__ __align__(16) __nv_bfloat16 sBh[128*40];
    __shared__ __align__(16) __nv_bfloat16 sBl[128*40];

    const int tid  = threadIdx.x;
    const int lane = tid & 31;
    const int wid  = tid >> 5;
    const int wm   = wid & 1;        // 0..1  (M)
    const int wn   = wid >> 1;       // 0..3  (N)
    const int b    = blockIdx.z;
    const int m0   = blockIdx.y * TM;
    const int n0   = blockIdx.x * TN;

    const __nv_bfloat16* Abh = Ah + (size_t)b * aBatch;
    const __nv_bfloat16* Abl = Al + (size_t)b * aBatch;

    float acc[4][4][4];
    #pragma unroll
    for (int i = 0; i < 4; i++)
        #pragma unroll
        for (int j = 0; j < 4; j++)
            #pragma unroll
            for (int r = 0; r < 4; r++) acc[i][j][r] = 0.f;

    // A-ldmatrix address (same every chunk)
    const int a_lrow = lane & 15;
    const int a_lcol = (lane >> 4) << 3;
    // B-nt ldmatrix: l = lane&15: row = nbase + (l&7), col = ks*16 + (l>>3)*8
    const int bl_ = lane & 15;

    const int NC = K / TKC;
    for (int kc = 0; kc < NC; kc++){
        // ---- stage global -> regs (issue before sync for overlap) ----
        uint4 avh[2], avl[2];
        int arow[2], acol[2];
        #pragma unroll
        for (int it = 0; it < 2; it++){
            int slot = it * 256 + tid;          // 0..511
            arow[it] = slot >> 2;               // 0..127
            acol[it] = (slot & 3) << 3;         // 0,8,16,24
            size_t go = (size_t)(m0 + arow[it]) * lda + kc * TKC + acol[it];
            avh[it] = *(const uint4*)(Abh + go);
            avl[it] = *(const uint4*)(Abl + go);
        }
        float4 bv[4];
        int bi0[4], bi1[4];                     // smem elem indices (hi/lo same)
        if (transB){
            #pragma unroll
            for (int it = 0; it < 4; it++){
                int slot = it * 256 + tid;      // 0..1023
                int k  = slot >> 5;             // 0..31
                int n4 = (slot & 31) << 2;      // 0..124
                int kg = kc * TKC + k;
                const float* g = (kg < K1)
                    ? (X1 + (size_t)b * x1B + (size_t)(x1Off + kg) * N_ + n0 + n4)
                    : (X2 + (size_t)b * x2B + (size_t)(x2Off + kg - K1) * N_ + n0 + n4);
                bv[it] = *(const float4*)g;
                bi0[it] = k * 136 + n4;
                bi1[it] = bi0[it] + 2;
            }
        } else {
            #pragma unroll
            for (int it = 0; it < 4; it++){
                int slot = it * 256 + tid;
                int n  = slot >> 3;             // 0..127
                int k4 = (slot & 7) << 2;       // 0..28
                const float* g = X1 + (size_t)b * x1B + (size_t)(n0 + n) * N_ + kc * TKC + k4;
                bv[it] = *(const float4*)g;
                bi0[it] = n * 40 + k4;
                bi1[it] = bi0[it] + 2;
            }
        }

        __syncthreads();   // previous chunk's mma done reading smem

        // ---- regs -> smem (A direct, B with fp32->hi/lo split) ----
        #pragma unroll
        for (int it = 0; it < 2; it++){
            *(uint4*)&sAh[arow[it]][acol[it]] = avh[it];
            *(uint4*)&sAl[arow[it]][acol[it]] = avl[it];
        }
        #pragma unroll
        for (int it = 0; it < 4; it++){
            float f[4] = {bv[it].x, bv[it].y, bv[it].z, bv[it].w};
            float h[4], l[4];
            #pragma unroll
            for (int j = 0; j < 4; j++){
                __nv_bfloat16 hb = __float2bfloat16_rn(f[j]);
                h[j] = __bfloat162float(hb);
                l[j] = f[j] - h[j];
            }
            *(uint32_t*)&sBh[bi0[it]] = pack_bf2(h[0], h[1]);
            *(uint32_t*)&sBh[bi1[it]] = pack_bf2(h[2], h[3]);
            *(uint32_t*)&sBl[bi0[it]] = pack_bf2(l[0], l[1]);
            *(uint32_t*)&sBl[bi1[it]] = pack_bf2(l[2], l[3]);
        }
        __syncthreads();

        // ---- MMA over 2 k16 steps ----
        #pragma unroll
        for (int ks = 0; ks < 2; ks++){
            uint32_t ah[4][4], al_[4][4], bh[4][2], blo[4][2];
            #pragma unroll
            for (int mt = 0; mt < 4; mt++){
                int r = wm*64 + mt*16 + a_lrow;
                int c = ks*16 + a_lcol;
                ldsm4(ah[mt],  smem_u32(&sAh[r][c]));
                ldsm4(al_[mt], smem_u32(&sAl[r][c]));
            }
            #pragma unroll
            for (int nt = 0; nt < 4; nt++){
                if (transB){
                    int idx = (ks*16 + bl_) * 136 + wn*32 + nt*8;
                    ldsm2t(bh[nt],  smem_u32(&sBh[idx]));
                    ldsm2t(blo[nt], smem_u32(&sBl[idx]));
                } else {
                    int idx = (wn*32 + nt*8 + (bl_ & 7)) * 40 + ks*16 + ((bl_ >> 3) << 3);
                    ldsm2(bh[nt],  smem_u32(&sBh[idx]));
                    ldsm2(blo[nt], smem_u32(&sBl[idx]));
                }
            }
            #pragma unroll
            for (int mt = 0; mt < 4; mt++)
                #pragma unroll
                for (int nt = 0; nt < 4; nt++){
                    mma16816(acc[mt][nt], ah[mt],  bh[nt]);
                    mma16816(acc[mt][nt], ah[mt],  blo[nt]);
                    mma16816(acc[mt][nt], al_[mt], bh[nt]);
                }
        }
    }

    // ---- epilogue ----
    const int g  = lane >> 2;
    const int t  = lane & 3;
    #pragma unroll
    for (int mt = 0; mt < 4; mt++){
        int m = m0 + wm*64 + mt*16 + g;
        float bi_lo = bias ? bias[m]     : 0.f;
        float bi_hi = bias ? bias[m + 8] : 0.f;
        #pragma unroll
        for (int nt = 0; nt < 4; nt++){
            int nn = n0 + wn*32 + nt*8 + 2*t;
            size_t off0 = (size_t)b * yB + (size_t)m * yStride + nn;
            size_t off1 = off0 + (size_t)8 * yStride;
            if (epiMode == 0){
                float2 o0, o1;
                o0.x = acc[mt][nt][0] * scale + bi_lo;
                o0.y = acc[mt][nt][1] * scale + bi_lo;
                o1.x = acc[mt][nt][2] * scale + bi_hi;
                o1.y = acc[mt][nt][3] * scale + bi_hi;
                *(float2*)(Y + off0) = o0;
                *(float2*)(Y + off1) = o1;
            } else {
                float2 gp0 = *(const float2*)(Egp + off0);
                float2 gp1 = *(const float2*)(Egp + off1);
                float2 y0  = *(const float2*)(Ey  + off0);
                float2 y1  = *(const float2*)(Ey  + off1);
                float s0 = 1.f/(1.f+__expf(-gp0.x));
                float s1 = 1.f/(1.f+__expf(-gp0.y));
                float s2 = 1.f/(1.f+__expf(-gp1.x));
                float s3 = 1.f/(1.f+__expf(-gp1.y));
                float2 o0, o1;
                o0.x = y0.x + s0 * ((acc[mt][nt][0] + bi_lo) - y0.x);
                o0.y = y0.y + s1 * ((acc[mt][nt][1] + bi_lo) - y0.y);
                o1.x = y1.x + s2 * ((acc[mt][nt][2] + bi_hi) - y1.x);
                o1.y = y1.y + s3 * ((acc[mt][nt][3] + bi_hi) - y1.y);
                *(float2*)(Y + off0) = o0;
                *(float2*)(Y + off1) = o1;
            }
        }
    }
}

// ---------------------------------------------------------------------------
__global__ void split_w(const float* __restrict__ s,
                        __nv_bfloat16* __restrict__ h,
                        __nv_bfloat16* __restrict__ l, int n)
{
    int i = blockIdx.x * 256 + threadIdx.x;
    if (i < n){
        float v = s[i];
        __nv_bfloat16 hh = __float2bfloat16_rn(v);
        h[i] = hh;
        l[i] = __float2bfloat16_rn(v - __bfloat162float(hh));
    }
}

// ---------------------------------------------------------------------------
__global__ void softmax_q(const float* __restrict__ qkv,
                          const float* __restrict__ mqk,
                          __nv_bfloat16* __restrict__ qh_h,
                          __nv_bfloat16* __restrict__ qh_l)
{
    __shared__ float red[8];
    __shared__ float bc;
    const int row = blockIdx.x;
    const int b = row >> 9, c = row & 511;
    const float* q  = qkv + ((size_t)b*1536 + c) * (size_t)N_;
    const float* mq = mqk + ((size_t)b*1024 + c) * (size_t)N_;
    const size_t base = (size_t)row * N_;

    float v[16];
    float mx = -1e30f;
    #pragma unroll
    for (int i = 0; i < 16; i++){
        int idx = threadIdx.x + (i << 8);
        float tv = -fmaxf(q[idx] * mq[idx], 0.f);
        v[i] = tv;
        mx = fmaxf(mx, tv);
    }
    #pragma unroll
    for (int off = 16; off; off >>= 1)
        mx = fmaxf(mx, __shfl_xor_sync(0xffffffffu, mx, off));
    if ((threadIdx.x & 31) == 0) red[threadIdx.x >> 5] = mx;
    __syncthreads();
    if (threadIdx.x == 0){
        float tv = red[0];
        #pragma unroll
        for (int i = 1; i < 8; i++) tv = fmaxf(tv, red[i]);
        bc = tv;
    }
    __syncthreads();
    mx = bc;

    float sm = 0.f;
    #pragma unroll
    for (int i = 0; i < 16; i++){
        v[i] = __expf(v[i] - mx);
        sm += v[i];
    }
    #pragma unroll
    for (int off = 16; off; off >>= 1)
        sm += __shfl_xor_sync(0xffffffffu, sm, off);
    __syncthreads();
    if ((threadIdx.x & 31) == 0) red[threadIdx.x >> 5] = sm;
    __syncthreads();
    if (threadIdx.x == 0){
        float tv = 0.f;
        #pragma unroll
        for (int i = 0; i < 8; i++) tv += red[i];
        bc = tv;
    }
    __syncthreads();
    const float rinv = 1.f / bc;
    #pragma unroll
    for (int i = 0; i < 16; i++){
        int idx = threadIdx.x + (i << 8);
        float f = v[i] * rinv;
        __nv_bfloat16 h = __float2bfloat16_rn(f);
        qh_h[base + idx] = h;
        qh_l[base + idx] = __float2bfloat16_rn(f - __bfloat162float(h));
    }
}

// ---------------------------------------------------------------------------
__global__ void relu_k(const float* __restrict__ qkv,
                       const float* __restrict__ mqk,
                       float* __restrict__ kh)
{
    const int row = blockIdx.x;
    const int b = row >> 9, c = row & 511;
    const float4* k4 = (const float4*)(qkv + ((size_t)b*1536 + 512 + c) * (size_t)N_);
    const float4* m4 = (const float4*)(mqk + ((size_t)b*1024 + 512 + c) * (size_t)N_);
    float4* o4 = (float4*)(kh + (size_t)row * N_);
    for (int i = threadIdx.x; i < N_/4; i += 256){
        float4 a = k4[i], m = m4[i], r;
        r.x = fmaxf(a.x * m.x, 0.f);
        r.y = fmaxf(a.y * m.y, 0.f);
        r.z = fmaxf(a.z * m.z, 0.f);
        r.w = fmaxf(a.w * m.w, 0.f);
        o4[i] = r;
    }
}

// ---------------------------------------------------------------------------
__global__ void softmax_attn(float* __restrict__ S,
                             __nv_bfloat16* __restrict__ ah,
                             __nv_bfloat16* __restrict__ al)
{
    __shared__ float red[4];
    __shared__ float bc;
    const int row = blockIdx.x;
    float* p = S + (size_t)row * 512;
    const size_t base = (size_t)row * 512;

    float v[4];
    float mx = -1e30f;
    #pragma unroll
    for (int i = 0; i < 4; i++){
        int idx = threadIdx.x + (i << 7);
        v[i] = p[idx];
        mx = fmaxf(mx, v[i]);
    }
    #pragma unroll
    for (int off = 16; off; off >>= 1)
        mx = fmaxf(mx, __shfl_xor_sync(0xffffffffu, mx, off));
    if ((threadIdx.x & 31) == 0) red[threadIdx.x >> 5] = mx;
    __syncthreads();
    if (threadIdx.x == 0)
        bc = fmaxf(fmaxf(red[0], red[1]), fmaxf(red[2], red[3]));
    __syncthreads();
    mx = bc;

    float sm = 0.f;
    #pragma unroll
    for (int i = 0; i < 4; i++){
        v[i] = __expf(v[i] - mx);
        sm += v[i];
    }
    #pragma unroll
    for (int off = 16; off; off >>= 1)
        sm += __shfl_xor_sync(0xffffffffu, sm, off);
    __syncthreads();
    if ((threadIdx.x & 31) == 0) red[threadIdx.x >> 5] = sm;
    __syncthreads();
    if (threadIdx.x == 0) bc = red[0] + red[1] + red[2] + red[3];
    __syncthreads();
    const float rinv = 1.f / bc;
    #pragma unroll
    for (int i = 0; i < 4; i++){
        int idx = threadIdx.x + (i << 7);
        float f = v[i] * rinv;
        p[idx] = f;
        __nv_bfloat16 h = __float2bfloat16_rn(f);
        ah[base + idx] = h;
        al[base + idx] = __float2bfloat16_rn(f - __bfloat162float(h));
    }
}

// ---------------------------------------------------------------------------
extern "C" void kernel_launch(void* const* d_in, const int* in_sizes, int n_in,
                              void* d_out, int out_size)
{
    const float* x    = (const float*)d_in[0];
    const float* Wqkv = (const float*)d_in[1];
    const float* bqkv = (const float*)d_in[2];
    const float* Wm   = (const float*)d_in[3];
    const float* bm   = (const float*)d_in[4];
    const float* Wg   = (const float*)d_in[5];
    const float* bg   = (const float*)d_in[6];
    const float* Wr   = (const float*)d_in[7];
    const float* br   = (const float*)d_in[8];

    float* out  = (float*)d_out;
    float* attn = out + (size_t)B_ * C_ * N_;

    float *p_qkv, *p_mqk, *p_kh, *p_y, *p_gp;
    __nv_bfloat16 *p_qh_h, *p_qh_l, *p_at_h, *p_at_l;
    __nv_bfloat16 *wqkv_h, *wqkv_l, *wm_h, *wm_l, *wg_h, *wg_l, *wr_h, *wr_l;
    cudaGetSymbolAddress((void**)&p_qkv, g_qkv);
    cudaGetSymbolAddress((void**)&p_mqk, g_mqk);
    cudaGetSymbolAddress((void**)&p_kh,  g_kh);
    cudaGetSymbolAddress((void**)&p_y,   g_y);
    cudaGetSymbolAddress((void**)&p_gp,  g_gp);
    cudaGetSymbolAddress((void**)&p_qh_h, g_qh_h);
    cudaGetSymbolAddress((void**)&p_qh_l, g_qh_l);
    cudaGetSymbolAddress((void**)&p_at_h, g_at_h);
    cudaGetSymbolAddress((void**)&p_at_l, g_at_l);
    cudaGetSymbolAddress((void**)&wqkv_h, g_wqkv_h);
    cudaGetSymbolAddress((void**)&wqkv_l, g_wqkv_l);
    cudaGetSymbolAddress((void**)&wm_h,   g_wm_h);
    cudaGetSymbolAddress((void**)&wm_l,   g_wm_l);
    cudaGetSymbolAddress((void**)&wg_h,   g_wg_h);
    cudaGetSymbolAddress((void**)&wg_l,   g_wg_l);
    cudaGetSymbolAddress((void**)&wr_h,   g_wr_h);
    cudaGetSymbolAddress((void**)&wr_l,   g_wr_l);

    const size_t sBCN = (size_t)C_ * N_;
    const size_t s3CN = (size_t)3*C_ * N_;
    const size_t s2CN = (size_t)2*C_ * N_;

    // 0) split weights into bf16 hi/lo
    split_w<<<(3*C_*C_ + 255)/256, 256>>>(Wqkv, wqkv_h, wqkv_l, 3*C_*C_);
    split_w<<<(2*C_*C_ + 255)/256, 256>>>(Wm,   wm_h,   wm_l,   2*C_*C_);
    split_w<<<(2*C_*C_ + 255)/256, 256>>>(Wg,   wg_h,   wg_l,   2*C_*C_);
    split_w<<<(  C_*C_ + 255)/256, 256>>>(Wr,   wr_h,   wr_l,     C_*C_);

    // 1) qkv = Wqkv @ x + bqkv
    mma_gemm<<<dim3(N_/TN, 3*C_/TM, B_), 256>>>(
        wqkv_h, wqkv_l, C_, 0,
        x, sBCN, 0, C_, x, sBCN, 0,
        bqkv, 1.f, p_qkv, s3CN, N_, C_, 1, nullptr, nullptr, 0);

    // 2) mqk = Wm @ v + bm
    mma_gemm<<<dim3(N_/TN, 2*C_/TM, B_), 256>>>(
        wm_h, wm_l, C_, 0,
        p_qkv, s3CN, 2*C_, C_, p_qkv, s3CN, 2*C_,
        bm, 1.f, p_mqk, s2CN, N_, C_, 1, nullptr, nullptr, 0);

    // 3) _q softmax -> bf16 hi/lo
    softmax_q<<<NROWS, 256>>>(p_qkv, p_mqk, p_qh_h, p_qh_l);

    // 4) _k = relu(k*mk)  (fp32)
    relu_k<<<NROWS, 256>>>(p_qkv, p_mqk, p_kh);

    // 5) scores = _q @ _k^T / sqrt(C)   (NT, K=4096)
    mma_gemm<<<dim3(C_/TN, C_/TM, B_), 256>>>(
        p_qh_h, p_qh_l, N_, sBCN,
        p_kh, sBCN, 0, N_, p_kh, sBCN, 0,
        nullptr, 1.0f/sqrtf((float)C_), attn, (size_t)C_*C_, C_, N_, 0,
        nullptr, nullptr, 0);

    // 6) attn = softmax(scores) in-place + bf16 hi/lo
    softmax_attn<<<NROWS, 128>>>(attn, p_at_h, p_at_l);

    // 7) y = attn @ v
    mma_gemm<<<dim3(N_/TN, C_/TM, B_), 256>>>(
        p_at_h, p_at_l, C_, (size_t)C_*C_,
        p_qkv, s3CN, 2*C_, C_, p_qkv, s3CN, 2*C_,
        nullptr, 1.f, p_y, sBCN, N_, C_, 1, nullptr, nullptr, 0);

    // 8) gpre = Wg @ [y; x] + bg   (fused K=1024)
    mma_gemm<<<dim3(N_/TN, C_/TM, B_), 256>>>(
        wg_h, wg_l, 2*C_, 0,
        p_y, sBCN, 0, C_, x, sBCN, 0,
        bg, 1.f, p_gp, sBCN, N_, 2*C_, 1, nullptr, nullptr, 0);

    // 9) r = Wr @ x + br fused with: out = y + sigmoid(gp)*(r - y)
    mma_gemm<<<dim3(N_/TN, C_/TM, B_), 256>>>(
        wr_h, wr_l, C_, 0,
        x, sBCN, 0, C_, x, sBCN, 0,
        br, 1.f, out, sBCN, N_, C_, 1, p_gp, p_y, 1);
}

// round 4
// speedup vs baseline: 2.9801x; 1.6891x over previous
#include <cuda_runtime.h>
#include <cuda_bf16.h>
#include <math.h>
#include <stdint.h>
#include <stddef.h>

#define B_ 16
#define C_ 512
#define N_ 4096
#define NROWS (B_*C_)

// block tile
#define TM 128
#define TN 128
#define TKC 32          // K per chunk (bf16 elems)

// dynamic smem: per stage A(hi,lo)=2*128*40*2B, B(hi,lo)=2*128*40*2B
#define A_PAD 40
#define B_PAD_T 136
#define HALF_BYTES 10240                 // 128*40*2
#define STG_BYTES (4*HALF_BYTES)         // 40960
#define SMEM_TOTAL (2*STG_BYTES)         // 81920

// ---------------- scratch (device globals) ----------------
__device__ float g_qkv[(size_t)B_*3*C_*N_];
__device__ float g_mqk[(size_t)B_*2*C_*N_];
__device__ float g_y  [(size_t)B_*C_*N_];
__device__ float g_gp [(size_t)B_*C_*N_];
__device__ __nv_bfloat16 g_xh [(size_t)B_*C_*N_], g_xl [(size_t)B_*C_*N_];
__device__ __nv_bfloat16 g_vh [(size_t)B_*C_*N_], g_vl [(size_t)B_*C_*N_];
__device__ __nv_bfloat16 g_khh[(size_t)B_*C_*N_], g_khl[(size_t)B_*C_*N_];
__device__ __nv_bfloat16 g_yh [(size_t)B_*C_*N_], g_yl [(size_t)B_*C_*N_];
__device__ __nv_bfloat16 g_qh_h[(size_t)B_*C_*N_], g_qh_l[(size_t)B_*C_*N_];
__device__ __nv_bfloat16 g_at_h[(size_t)B_*C_*C_], g_at_l[(size_t)B_*C_*C_];
__device__ __nv_bfloat16 g_wqkv_h[3*C_*C_], g_wqkv_l[3*C_*C_];
__device__ __nv_bfloat16 g_wm_h[2*C_*C_],   g_wm_l[2*C_*C_];
__device__ __nv_bfloat16 g_wg_h[C_*2*C_],   g_wg_l[C_*2*C_];
__device__ __nv_bfloat16 g_wr_h[C_*C_],     g_wr_l[C_*C_];

// ---------------- PTX helpers (portable) ----------------
__device__ __forceinline__ uint32_t smem_u32(const void* p){
    uint32_t a;
    asm("{ .reg .u64 t; cvta.to.shared.u64 t, %1; cvt.u32.u64 %0, t; }"
        : "=r"(a) : "l"(p));
    return a;
}
__device__ __forceinline__ void cpa16(uint32_t dst, const void* src){
    asm volatile("cp.async.cg.shared.global [%0], [%1], 16;"
                 :: "r"(dst), "l"(src) : "memory");
}
__device__ __forceinline__ void cp_commit(){
    asm volatile("cp.async.commit_group;" ::: "memory");
}
__device__ __forceinline__ void cp_wait1(){
    asm volatile("cp.async.wait_group 1;" ::: "memory");
}
__device__ __forceinline__ void cp_wait0(){
    asm volatile("cp.async.wait_group 0;" ::: "memory");
}
__device__ __forceinline__ void ldsm4(uint32_t* r, uint32_t addr){
    asm volatile("ldmatrix.sync.aligned.m8n8.x4.shared.b16 {%0,%1,%2,%3}, [%4];"
        : "=r"(r[0]), "=r"(r[1]), "=r"(r[2]), "=r"(r[3]) : "r"(addr));
}
__device__ __forceinline__ void ldsm2(uint32_t* r, uint32_t addr){
    asm volatile("ldmatrix.sync.aligned.m8n8.x2.shared.b16 {%0,%1}, [%2];"
        : "=r"(r[0]), "=r"(r[1]) : "r"(addr));
}
__device__ __forceinline__ void ldsm2t(uint32_t* r, uint32_t addr){
    asm volatile("ldmatrix.sync.aligned.m8n8.x2.trans.shared.b16 {%0,%1}, [%2];"
        : "=r"(r[0]), "=r"(r[1]) : "r"(addr));
}
__device__ __forceinline__ void mma16816(float* c, const uint32_t* a, const uint32_t* b){
    asm volatile(
        "mma.sync.aligned.m16n8k16.row.col.f32.bf16.bf16.f32 "
        "{%0,%1,%2,%3}, {%4,%5,%6,%7}, {%8,%9}, {%0,%1,%2,%3};"
        : "+f"(c[0]), "+f"(c[1]), "+f"(c[2]), "+f"(c[3])
        : "r"(a[0]), "r"(a[1]), "r"(a[2]), "r"(a[3]), "r"(b[0]), "r"(b[1]));
}
__device__ __forceinline__ uint32_t pack_bf2(float x, float y){
    __nv_bfloat162 p(__float2bfloat16_rn(x), __float2bfloat16_rn(y));
    return *(uint32_t*)&p;
}
__device__ __forceinline__ uint32_t split_pack_h(float x, float y, uint32_t* lo){
    __nv_bfloat16 hx = __float2bfloat16_rn(x);
    __nv_bfloat16 hy = __float2bfloat16_rn(y);
    *lo = pack_bf2(x - __bfloat162float(hx), y - __bfloat162float(hy));
    __nv_bfloat162 p(hx, hy);
    return *(uint32_t*)&p;
}

// ---------------------------------------------------------------------------
// Pipelined bf16 split-operand GEMM on mma.sync + cp.async double buffering.
//   val = scale * sum_k (Ah+Al)[m,k] * (Bh+Bl)[k,n]  (3-term)  + bias[m]
// A: bf16 hi/lo row-major (lda, aBatch).
// B: bf16 hi/lo. transB=1: MN-major rows k (stride N_); rows >= K1 from B2.
//    transB=0: K-major rows n (stride N_), NT GEMM.
// Outputs: fp32 Y (optional); bf16 split Yh/Yl for rows >= yhOff (optional).
// epiMode 1: out = Ey + sigmoid(Egp) * (val - Ey)
// ---------------------------------------------------------------------------
__global__ void __launch_bounds__(256, 2) mma_gemm(
    const __nv_bfloat16* __restrict__ Ah, const __nv_bfloat16* __restrict__ Al,
    int lda, size_t aBatch,
    const __nv_bfloat16* __restrict__ B1h, const __nv_bfloat16* __restrict__ B1l,
    size_t b1B,
    const __nv_bfloat16* __restrict__ B2h, const __nv_bfloat16* __restrict__ B2l,
    size_t b2B, int K1,
    const float* __restrict__ bias, float scale,
    float* __restrict__ Y, size_t yB, int yStride,
    __nv_bfloat16* __restrict__ Yh, __nv_bfloat16* __restrict__ Yl,
    size_t yhB, int yhOff,
    const float* __restrict__ Egp, const float* __restrict__ Ey, int epiMode,
    int K, int transB)
{
    extern __shared__ char smem[];
    const uint32_t sbase = smem_u32(smem);

    const int tid  = threadIdx.x;
    const int lane = tid & 31;
    const int wid  = tid >> 5;
    const int wm   = wid & 1;
    const int wn   = wid >> 1;
    const int b    = blockIdx.z;
    const int m0   = blockIdx.y * TM;
    const int n0   = blockIdx.x * TN;

    const __nv_bfloat16* Abh = Ah + (size_t)b * aBatch;
    const __nv_bfloat16* Abl = Al + (size_t)b * aBatch;

    const int NC = K / TKC;

    // ---- stage loader ----
    auto load_stage = [&](int s, int kc){
        const uint32_t sa = sbase + s * STG_BYTES;
        // A hi/lo: 128 rows x 32 k
        #pragma unroll
        for (int it = 0; it < 2; it++){
            int slot = it * 256 + tid;
            int row = slot >> 2, c8 = (slot & 3) << 3;
            size_t go = (size_t)(m0 + row) * lda + kc * TKC + c8;
            uint32_t d = sa + 2 * (row * A_PAD + c8);
            cpa16(d, Abh + go);
            cpa16(d + HALF_BYTES, Abl + go);
        }
        if (transB){
            #pragma unroll
            for (int it = 0; it < 2; it++){
                int slot = it * 256 + tid;
                int k = slot >> 4, n8 = (slot & 15) << 3;
                int kg = kc * TKC + k;
                const __nv_bfloat16 *sh, *sl;
                if (kg < K1){
                    size_t go = (size_t)b * b1B + (size_t)kg * N_ + n0 + n8;
                    sh = B1h + go; sl = B1l + go;
                } else {
                    size_t go = (size_t)b * b2B + (size_t)(kg - K1) * N_ + n0 + n8;
                    sh = B2h + go; sl = B2l + go;
                }
                uint32_t d = sa + 2*HALF_BYTES + 2 * (k * B_PAD_T + n8);
                cpa16(d, sh);
                cpa16(d + HALF_BYTES, sl);
            }
        } else {
            #pragma unroll
            for (int it = 0; it < 2; it++){
                int slot = it * 256 + tid;
                int n = slot >> 2, k8 = (slot & 3) << 3;
                size_t go = (size_t)b * b1B + (size_t)(n0 + n) * N_ + kc * TKC + k8;
                uint32_t d = sa + 2*HALF_BYTES + 2 * (n * A_PAD + k8);
                cpa16(d, B1h + go);
                cpa16(d + HALF_BYTES, B1l + go);
            }
        }
        cp_commit();
    };

    float acc[4][4][4];
    #pragma unroll
    for (int i = 0; i < 4; i++)
        #pragma unroll
        for (int j = 0; j < 4; j++)
            #pragma unroll
            for (int r = 0; r < 4; r++) acc[i][j][r] = 0.f;

    const int a_lrow = lane & 15;
    const int a_lcol = (lane >> 4) << 3;
    const int bl_    = lane & 15;

    load_stage(0, 0);
    if (NC > 1) load_stage(1, 1);

    for (int kc = 0; kc < NC; kc++){
        if (kc + 1 < NC) cp_wait1(); else cp_wait0();
        __syncthreads();

        const uint32_t sa = sbase + (kc & 1) * STG_BYTES;
        const uint32_t sb = sa + 2*HALF_BYTES;

        #pragma unroll
        for (int ks = 0; ks < 2; ks++){
            uint32_t ah[4][4], al_[4][4], bh[4][2], blo[4][2];
            #pragma unroll
            for (int mt = 0; mt < 4; mt++){
                uint32_t ad = sa + 2 * ((wm*64 + mt*16 + a_lrow) * A_PAD + ks*16 + a_lcol);
                ldsm4(ah[mt],  ad);
                ldsm4(al_[mt], ad + HALF_BYTES);
            }
            #pragma unroll
            for (int nt = 0; nt < 4; nt++){
                if (transB){
                    uint32_t bd = sb + 2 * ((ks*16 + bl_) * B_PAD_T + wn*32 + nt*8);
                    ldsm2t(bh[nt],  bd);
                    ldsm2t(blo[nt], bd + HALF_BYTES);
                } else {
                    uint32_t bd = sb + 2 * ((wn*32 + nt*8 + (bl_ & 7)) * A_PAD + ks*16 + ((bl_ >> 3) << 3));
                    ldsm2(bh[nt],  bd);
                    ldsm2(blo[nt], bd + HALF_BYTES);
                }
            }
            #pragma unroll
            for (int mt = 0; mt < 4; mt++)
                #pragma unroll
                for (int nt = 0; nt < 4; nt++){
                    mma16816(acc[mt][nt], ah[mt],  bh[nt]);
                    mma16816(acc[mt][nt], ah[mt],  blo[nt]);
                    mma16816(acc[mt][nt], al_[mt], bh[nt]);
                }
        }
        __syncthreads();
        if (kc + 2 < NC) load_stage(kc & 1, kc + 2);
    }

    // ---- epilogue ----
    const int g = lane >> 2;
    const int t = lane & 3;
    #pragma unroll
    for (int mt = 0; mt < 4; mt++){
        int m = m0 + wm*64 + mt*16 + g;
        float bi_lo = bias ? bias[m]     : 0.f;
        float bi_hi = bias ? bias[m + 8] : 0.f;
        #pragma unroll
        for (int nt = 0; nt < 4; nt++){
            int nn = n0 + wn*32 + nt*8 + 2*t;
            float v00 = acc[mt][nt][0] * scale + bi_lo;
            float v01 = acc[mt][nt][1] * scale + bi_lo;
            float v10 = acc[mt][nt][2] * scale + bi_hi;
            float v11 = acc[mt][nt][3] * scale + bi_hi;
            size_t off0 = (size_t)b * yB + (size_t)m * yStride + nn;
            size_t off1 = off0 + (size_t)8 * yStride;
            if (epiMode == 1){
                float2 gp0 = *(const float2*)(Egp + off0);
                float2 gp1 = *(const float2*)(Egp + off1);
                float2 y0  = *(const float2*)(Ey  + off0);
                float2 y1  = *(const float2*)(Ey  + off1);
                float s0 = 1.f/(1.f+__expf(-gp0.x));
                float s1 = 1.f/(1.f+__expf(-gp0.y));
                float s2 = 1.f/(1.f+__expf(-gp1.x));
                float s3 = 1.f/(1.f+__expf(-gp1.y));
                float2 o0, o1;
                o0.x = y0.x + s0 * (v00 - y0.x);
                o0.y = y0.y + s1 * (v01 - y0.y);
                o1.x = y1.x + s2 * (v10 - y1.x);
                o1.y = y1.y + s3 * (v11 - y1.y);
                *(float2*)(Y + off0) = o0;
                *(float2*)(Y + off1) = o1;
            } else {
                if (Y){
                    float2 o0 = {v00, v01}, o1 = {v10, v11};
                    *(float2*)(Y + off0) = o0;
                    *(float2*)(Y + off1) = o1;
                }
                if (Yh && m >= yhOff){
                    size_t so0 = (size_t)b * yhB + (size_t)(m - yhOff) * N_ + nn;
                    size_t so1 = so0 + (size_t)8 * N_;
                    uint32_t l0, l1;
                    uint32_t h0 = split_pack_h(v00, v01, &l0);
                    uint32_t h1 = split_pack_h(v10, v11, &l1);
                    *(uint32_t*)(Yh + so0) = h0;
                    *(uint32_t*)(Yl + so0) = l0;
                    *(uint32_t*)(Yh + so1) = h1;
                    *(uint32_t*)(Yl + so1) = l1;
                }
            }
        }
    }
}

// ---------------------------------------------------------------------------
__global__ void split_w(const float* __restrict__ s,
                        __nv_bfloat16* __restrict__ h,
                        __nv_bfloat16* __restrict__ l, int n)
{
    int i = blockIdx.x * 256 + threadIdx.x;
    if (i < n){
        float v = s[i];
        __nv_bfloat16 hh = __float2bfloat16_rn(v);
        h[i] = hh;
        l[i] = __float2bfloat16_rn(v - __bfloat162float(hh));
    }
}

// ---------------------------------------------------------------------------
__global__ void softmax_q(const float* __restrict__ qkv,
                          const float* __restrict__ mqk,
                          __nv_bfloat16* __restrict__ qh_h,
                          __nv_bfloat16* __restrict__ qh_l)
{
    __shared__ float red[8];
    __shared__ float bc;
    const int row = blockIdx.x;
    const int b = row >> 9, c = row & 511;
    const float* q  = qkv + ((size_t)b*1536 + c) * (size_t)N_;
    const float* mq = mqk + ((size_t)b*1024 + c) * (size_t)N_;
    const size_t base = (size_t)row * N_;

    float v[16];
    float mx = -1e30f;
    #pragma unroll
    for (int i = 0; i < 16; i++){
        int idx = threadIdx.x + (i << 8);
        float tv = -fmaxf(q[idx] * mq[idx], 0.f);
        v[i] = tv;
        mx = fmaxf(mx, tv);
    }
    #pragma unroll
    for (int off = 16; off; off >>= 1)
        mx = fmaxf(mx, __shfl_xor_sync(0xffffffffu, mx, off));
    if ((threadIdx.x & 31) == 0) red[threadIdx.x >> 5] = mx;
    __syncthreads();
    if (threadIdx.x == 0){
        float tv = red[0];
        #pragma unroll
        for (int i = 1; i < 8; i++) tv = fmaxf(tv, red[i]);
        bc = tv;
    }
    __syncthreads();
    mx = bc;

    float sm = 0.f;
    #pragma unroll
    for (int i = 0; i < 16; i++){
        v[i] = __expf(v[i] - mx);
        sm += v[i];
    }
    #pragma unroll
    for (int off = 16; off; off >>= 1)
        sm += __shfl_xor_sync(0xffffffffu, sm, off);
    __syncthreads();
    if ((threadIdx.x & 31) == 0) red[threadIdx.x >> 5] = sm;
    __syncthreads();
    if (threadIdx.x == 0){
        float tv = 0.f;
        #pragma unroll
        for (int i = 0; i < 8; i++) tv += red[i];
        bc = tv;
    }
    __syncthreads();
    const float rinv = 1.f / bc;
    #pragma unroll
    for (int i = 0; i < 16; i++){
        int idx = threadIdx.x + (i << 8);
        float f = v[i] * rinv;
        __nv_bfloat16 h = __float2bfloat16_rn(f);
        qh_h[base + idx] = h;
        qh_l[base + idx] = __float2bfloat16_rn(f - __bfloat162float(h));
    }
}

// ---------------------------------------------------------------------------
// _k = relu(k*mk) -> bf16 hi/lo
// ---------------------------------------------------------------------------
__global__ void relu_k(const float* __restrict__ qkv,
                       const float* __restrict__ mqk,
                       __nv_bfloat16* __restrict__ khh,
                       __nv_bfloat16* __restrict__ khl)
{
    const int row = blockIdx.x;
    const int b = row >> 9, c = row & 511;
    const float4* k4 = (const float4*)(qkv + ((size_t)b*1536 + 512 + c) * (size_t)N_);
    const float4* m4 = (const float4*)(mqk + ((size_t)b*1024 + 512 + c) * (size_t)N_);
    uint32_t* oh = (uint32_t*)(khh + (size_t)row * N_);
    uint32_t* ol = (uint32_t*)(khl + (size_t)row * N_);
    for (int i = threadIdx.x; i < N_/4; i += 256){
        float4 a = k4[i], m = m4[i];
        float r0 = fmaxf(a.x * m.x, 0.f);
        float r1 = fmaxf(a.y * m.y, 0.f);
        float r2 = fmaxf(a.z * m.z, 0.f);
        float r3 = fmaxf(a.w * m.w, 0.f);
        uint32_t l0, l1;
        uint32_t h0 = split_pack_h(r0, r1, &l0);
        uint32_t h1 = split_pack_h(r2, r3, &l1);
        oh[2*i]   = h0; oh[2*i+1] = h1;
        ol[2*i]   = l0; ol[2*i+1] = l1;
    }
}

// ---------------------------------------------------------------------------
__global__ void softmax_attn(float* __restrict__ S,
                             __nv_bfloat16* __restrict__ ah,
                             __nv_bfloat16* __restrict__ al)
{
    __shared__ float red[4];
    __shared__ float bc;
    const int row = blockIdx.x;
    float* p = S + (size_t)row * 512;
    const size_t base = (size_t)row * 512;

    float v[4];
    float mx = -1e30f;
    #pragma unroll
    for (int i = 0; i < 4; i++){
        int idx = threadIdx.x + (i << 7);
        v[i] = p[idx];
        mx = fmaxf(mx, v[i]);
    }
    #pragma unroll
    for (int off = 16; off; off >>= 1)
        mx = fmaxf(mx, __shfl_xor_sync(0xffffffffu, mx, off));
    if ((threadIdx.x & 31) == 0) red[threadIdx.x >> 5] = mx;
    __syncthreads();
    if (threadIdx.x == 0)
        bc = fmaxf(fmaxf(red[0], red[1]), fmaxf(red[2], red[3]));
    __syncthreads();
    mx = bc;

    float sm = 0.f;
    #pragma unroll
    for (int i = 0; i < 4; i++){
        v[i] = __expf(v[i] - mx);
        sm += v[i];
    }
    #pragma unroll
    for (int off = 16; off; off >>= 1)
        sm += __shfl_xor_sync(0xffffffffu, sm, off);
    __syncthreads();
    if ((threadIdx.x & 31) == 0) red[threadIdx.x >> 5] = sm;
    __syncthreads();
    if (threadIdx.x == 0) bc = red[0] + red[1] + red[2] + red[3];
    __syncthreads();
    const float rinv = 1.f / bc;
    #pragma unroll
    for (int i = 0; i < 4; i++){
        int idx = threadIdx.x + (i << 7);
        float f = v[i] * rinv;
        p[idx] = f;
        __nv_bfloat16 h = __float2bfloat16_rn(f);
        ah[base + idx] = h;
        al[base + idx] = __float2bfloat16_rn(f - __bfloat162float(h));
    }
}

// ---------------------------------------------------------------------------
extern "C" void kernel_launch(void* const* d_in, const int* in_sizes, int n_in,
                              void* d_out, int out_size)
{
    const float* x    = (const float*)d_in[0];
    const float* Wqkv = (const float*)d_in[1];
    const float* bqkv = (const float*)d_in[2];
    const float* Wm   = (const float*)d_in[3];
    const float* bm   = (const float*)d_in[4];
    const float* Wg   = (const float*)d_in[5];
    const float* bg   = (const float*)d_in[6];
    const float* Wr   = (const float*)d_in[7];
    const float* br   = (const float*)d_in[8];

    float* out  = (float*)d_out;
    float* attn = out + (size_t)B_ * C_ * N_;

    static int s_init = 0;
    if (!s_init){
        cudaFuncSetAttribute(mma_gemm, cudaFuncAttributeMaxDynamicSharedMemorySize, SMEM_TOTAL);
        s_init = 1;
    }

    float *p_qkv, *p_mqk, *p_y, *p_gp;
    __nv_bfloat16 *xh, *xl, *vh, *vl, *khh, *khl, *yh, *yl;
    __nv_bfloat16 *p_qh_h, *p_qh_l, *p_at_h, *p_at_l;
    __nv_bfloat16 *wqkv_h, *wqkv_l, *wm_h, *wm_l, *wg_h, *wg_l, *wr_h, *wr_l;
    cudaGetSymbolAddress((void**)&p_qkv, g_qkv);
    cudaGetSymbolAddress((void**)&p_mqk, g_mqk);
    cudaGetSymbolAddress((void**)&p_y,   g_y);
    cudaGetSymbolAddress((void**)&p_gp,  g_gp);
    cudaGetSymbolAddress((void**)&xh,  g_xh);  cudaGetSymbolAddress((void**)&xl,  g_xl);
    cudaGetSymbolAddress((void**)&vh,  g_vh);  cudaGetSymbolAddress((void**)&vl,  g_vl);
    cudaGetSymbolAddress((void**)&khh, g_khh); cudaGetSymbolAddress((void**)&khl, g_khl);
    cudaGetSymbolAddress((void**)&yh,  g_yh);  cudaGetSymbolAddress((void**)&yl,  g_yl);
    cudaGetSymbolAddress((void**)&p_qh_h, g_qh_h);
    cudaGetSymbolAddress((void**)&p_qh_l, g_qh_l);
    cudaGetSymbolAddress((void**)&p_at_h, g_at_h);
    cudaGetSymbolAddress((void**)&p_at_l, g_at_l);
    cudaGetSymbolAddress((void**)&wqkv_h, g_wqkv_h);
    cudaGetSymbolAddress((void**)&wqkv_l, g_wqkv_l);
    cudaGetSymbolAddress((void**)&wm_h,   g_wm_h);
    cudaGetSymbolAddress((void**)&wm_l,   g_wm_l);
    cudaGetSymbolAddress((void**)&wg_h,   g_wg_h);
    cudaGetSymbolAddress((void**)&wg_l,   g_wg_l);
    cudaGetSymbolAddress((void**)&wr_h,   g_wr_h);
    cudaGetSymbolAddress((void**)&wr_l,   g_wr_l);

    const size_t sBCN = (size_t)C_ * N_;
    const size_t s3CN = (size_t)3*C_ * N_;
    const size_t s2CN = (size_t)2*C_ * N_;

    // 0) split weights and x
    split_w<<<(3*C_*C_ + 255)/256, 256>>>(Wqkv, wqkv_h, wqkv_l, 3*C_*C_);
    split_w<<<(2*C_*C_ + 255)/256, 256>>>(Wm,   wm_h,   wm_l,   2*C_*C_);
    split_w<<<(2*C_*C_ + 255)/256, 256>>>(Wg,   wg_h,   wg_l,   2*C_*C_);
    split_w<<<(  C_*C_ + 255)/256, 256>>>(Wr,   wr_h,   wr_l,     C_*C_);
    split_w<<<((int)(B_*sBCN) + 255)/256, 256>>>(x, xh, xl, (int)(B_*sBCN));

    // 1) qkv = Wqkv @ x + bqkv ; also emit v (rows >= 2C) as bf16 split
    mma_gemm<<<dim3(N_/TN, 3*C_/TM, B_), 256, SMEM_TOTAL>>>(
        wqkv_h, wqkv_l, C_, 0,
        xh, xl, sBCN, nullptr, nullptr, 0, C_,
        bqkv, 1.f, p_qkv, s3CN, N_,
        vh, vl, sBCN, 2*C_,
        nullptr, nullptr, 0, C_, 1);

    // 2) mqk = Wm @ v + bm
    mma_gemm<<<dim3(N_/TN, 2*C_/TM, B_), 256, SMEM_TOTAL>>>(
        wm_h, wm_l, C_, 0,
        vh, vl, sBCN, nullptr, nullptr, 0, C_,
        bm, 1.f, p_mqk, s2CN, N_,
        nullptr, nullptr, 0, 0,
        nullptr, nullptr, 0, C_, 1);

    // 3) _q softmax -> bf16 hi/lo
    softmax_q<<<NROWS, 256>>>(p_qkv, p_mqk, p_qh_h, p_qh_l);

    // 4) _k = relu(k*mk) -> bf16 hi/lo
    relu_k<<<NROWS, 256>>>(p_qkv, p_mqk, khh, khl);

    // 5) scores = _q @ _k^T / sqrt(C)   (NT, K=4096)
    mma_gemm<<<dim3(C_/TN, C_/TM, B_), 256, SMEM_TOTAL>>>(
        p_qh_h, p_qh_l, N_, sBCN,
        khh, khl, sBCN, nullptr, nullptr, 0, N_,
        nullptr, 1.0f/sqrtf((float)C_), attn, (size_t)C_*C_, C_,
        nullptr, nullptr, 0, 0,
        nullptr, nullptr, 0, N_, 0);

    // 6) attn = softmax(scores) in-place + bf16 split
    softmax_attn<<<NROWS, 128>>>(attn, p_at_h, p_at_l);

    // 7) y = attn @ v ; fp32 y + bf16 split
    mma_gemm<<<dim3(N_/TN, C_/TM, B_), 256, SMEM_TOTAL>>>(
        p_at_h, p_at_l, C_, (size_t)C_*C_,
        vh, vl, sBCN, nullptr, nullptr, 0, C_,
        nullptr, 1.f, p_y, sBCN, N_,
        yh, yl, sBCN, 0,
        nullptr, nullptr, 0, C_, 1);

    // 8) gpre = Wg @ [y; x] + bg   (K=1024, two B sources)
    mma_gemm<<<dim3(N_/TN, C_/TM, B_), 256, SMEM_TOTAL>>>(
        wg_h, wg_l, 2*C_, 0,
        yh, yl, sBCN, xh, xl, sBCN, C_,
        bg, 1.f, p_gp, sBCN, N_,
        nullptr, nullptr, 0, 0,
        nullptr, nullptr, 0, 2*C_, 1);

    // 9) r = Wr @ x + br fused: out = y + sigmoid(gp)*(r - y)
    mma_gemm<<<dim3(N_/TN, C_/TM, B_), 256, SMEM_TOTAL>>>(
        wr_h, wr_l, C_, 0,
        xh, xl, sBCN, nullptr, nullptr, 0, C_,
        br, 1.f, out, sBCN, N_,
        nullptr, nullptr, 0, 0,
        p_gp, p_y, 1, C_, 1);
}

// round 6
// speedup vs baseline: 4.0412x; 1.3561x over previous
#include <cuda_runtime.h>
#include <cuda_fp16.h>
#include <math.h>
#include <stdint.h>
#include <stddef.h>

#define B_ 16
#define C_ 512
#define N_ 4096
#define NROWS (B_*C_)

// block tile
#define TM 128
#define TN 128
#define TKC 32

// smem layout (halves = fp16)
#define A_PAD 40
#define B_PAD_T 136
#define AH_BYTES 10240                    // 128*40*2
#define STG_BYTES (3*AH_BYTES)            // Ah + Al + B = 30720
#define NSTAGE 3
#define SMEM_TOTAL (NSTAGE*STG_BYTES)     // 92160

// ---------------- scratch (device globals) ----------------
__device__ float g_qkv[(size_t)B_*3*C_*N_];
__device__ float g_mqk[(size_t)B_*2*C_*N_];
__device__ float g_y  [(size_t)B_*C_*N_];
__device__ float g_gp [(size_t)B_*C_*N_];
__device__ __half g_xh [(size_t)B_*C_*N_];
__device__ __half g_vh [(size_t)B_*C_*N_];
__device__ __half g_khh[(size_t)B_*C_*N_];
__device__ __half g_yh [(size_t)B_*C_*N_];
__device__ __half g_qh_h[(size_t)B_*C_*N_], g_qh_l[(size_t)B_*C_*N_];
__device__ __half g_at_h[(size_t)B_*C_*C_], g_at_l[(size_t)B_*C_*C_];
__device__ __half g_wqkv_h[3*C_*C_], g_wqkv_l[3*C_*C_];
__device__ __half g_wm_h[2*C_*C_],   g_wm_l[2*C_*C_];
__device__ __half g_wg_h[C_*2*C_],   g_wg_l[C_*2*C_];
__device__ __half g_wr_h[C_*C_],     g_wr_l[C_*C_];

// ---------------- PTX helpers (portable) ----------------
__device__ __forceinline__ uint32_t smem_u32(const void* p){
    uint32_t a;
    asm("{ .reg .u64 t; cvta.to.shared.u64 t, %1; cvt.u32.u64 %0, t; }"
        : "=r"(a) : "l"(p));
    return a;
}
__device__ __forceinline__ void cpa16(uint32_t dst, const void* src){
    asm volatile("cp.async.cg.shared.global [%0], [%1], 16;"
                 :: "r"(dst), "l"(src) : "memory");
}
__device__ __forceinline__ void cp_commit(){
    asm volatile("cp.async.commit_group;" ::: "memory");
}
__device__ __forceinline__ void cp_wait1(){
    asm volatile("cp.async.wait_group 1;" ::: "memory");
}
__device__ __forceinline__ void cp_wait0(){
    asm volatile("cp.async.wait_group 0;" ::: "memory");
}
__device__ __forceinline__ void ldsm4(uint32_t* r, uint32_t addr){
    asm volatile("ldmatrix.sync.aligned.m8n8.x4.shared.b16 {%0,%1,%2,%3}, [%4];"
        : "=r"(r[0]), "=r"(r[1]), "=r"(r[2]), "=r"(r[3]) : "r"(addr));
}
__device__ __forceinline__ void ldsm2(uint32_t* r, uint32_t addr){
    asm volatile("ldmatrix.sync.aligned.m8n8.x2.shared.b16 {%0,%1}, [%2];"
        : "=r"(r[0]), "=r"(r[1]) : "r"(addr));
}
__device__ __forceinline__ void ldsm2t(uint32_t* r, uint32_t addr){
    asm volatile("ldmatrix.sync.aligned.m8n8.x2.trans.shared.b16 {%0,%1}, [%2];"
        : "=r"(r[0]), "=r"(r[1]) : "r"(addr));
}
__device__ __forceinline__ void mma16816(float* c, const uint32_t* a, const uint32_t* b){
    asm volatile(
        "mma.sync.aligned.m16n8k16.row.col.f32.f16.f16.f32 "
        "{%0,%1,%2,%3}, {%4,%5,%6,%7}, {%8,%9}, {%0,%1,%2,%3};"
        : "+f"(c[0]), "+f"(c[1]), "+f"(c[2]), "+f"(c[3])
        : "r"(a[0]), "r"(a[1]), "r"(a[2]), "r"(a[3]), "r"(b[0]), "r"(b[1]));
}
__device__ __forceinline__ uint32_t pack_h2(float x, float y){
    __half2 p(__float2half_rn(x), __float2half_rn(y));
    return *(uint32_t*)&p;
}

// ---------------------------------------------------------------------------
// 2-term fp16 split GEMM: val = scale * sum_k (Ah+Al)[m,k] * B[k,n] + bias[m]
// A: pre-split fp16 hi/lo, row-major (lda, aBatch).
// B: single fp16. transB=1: MN-major rows k (stride N_); rows >= K1 from B2.
//    transB=0: K-major rows n (stride N_)  (NT GEMM).
// Outputs: fp32 Y (optional); fp16 Yh for rows >= yhOff (optional).
// epiMode 1: out = Ey + sigmoid(Egp) * (val - Ey)
// 3-stage cp.async pipeline, one __syncthreads per chunk.
// ---------------------------------------------------------------------------
__global__ void __launch_bounds__(256, 2) mma_gemm(
    const __half* __restrict__ Ah, const __half* __restrict__ Al,
    int lda, size_t aBatch,
    const __half* __restrict__ B1, size_t b1B,
    const __half* __restrict__ B2, size_t b2B, int K1,
    const float* __restrict__ bias, float scale,
    float* __restrict__ Y, size_t yB, int yStride,
    __half* __restrict__ Yh, size_t yhB, int yhOff,
    const float* __restrict__ Egp, const float* __restrict__ Ey, int epiMode,
    int K, int transB)
{
    extern __shared__ char smem[];
    const uint32_t sbase = smem_u32(smem);

    const int tid  = threadIdx.x;
    const int lane = tid & 31;
    const int wid  = tid >> 5;
    const int wm   = wid & 1;
    const int wn   = wid >> 1;
    const int b    = blockIdx.z;
    const int m0   = blockIdx.y * TM;
    const int n0   = blockIdx.x * TN;

    const __half* Abh = Ah + (size_t)b * aBatch;
    const __half* Abl = Al + (size_t)b * aBatch;

    const int NC = K / TKC;

    auto load_stage = [&](int s, int kc){
        const uint32_t sa = sbase + s * STG_BYTES;
        #pragma unroll
        for (int it = 0; it < 2; it++){
            int slot = it * 256 + tid;
            int row = slot >> 2, c8 = (slot & 3) << 3;
            size_t go = (size_t)(m0 + row) * lda + kc * TKC + c8;
            uint32_t d = sa + 2 * (row * A_PAD + c8);
            cpa16(d, Abh + go);
            cpa16(d + AH_BYTES, Abl + go);
        }
        const uint32_t sb = sa + 2*AH_BYTES;
        if (transB){
            #pragma unroll
            for (int it = 0; it < 2; it++){
                int slot = it * 256 + tid;
                int k = slot >> 4, n8 = (slot & 15) << 3;
                int kg = kc * TKC + k;
                const __half* src = (kg < K1)
                    ? (B1 + (size_t)b * b1B + (size_t)kg * N_ + n0 + n8)
                    : (B2 + (size_t)b * b2B + (size_t)(kg - K1) * N_ + n0 + n8);
                cpa16(sb + 2 * (k * B_PAD_T + n8), src);
            }
        } else {
            #pragma unroll
            for (int it = 0; it < 2; it++){
                int slot = it * 256 + tid;
                int n = slot >> 2, k8 = (slot & 3) << 3;   // FIXED: 128 rows x 32 k
                size_t go = (size_t)b * b1B + (size_t)(n0 + n) * N_ + kc * TKC + k8;
                cpa16(sb + 2 * (n * A_PAD + k8), B1 + go);
            }
        }
        cp_commit();
    };

    float acc[4][4][4];
    #pragma unroll
    for (int i = 0; i < 4; i++)
        #pragma unroll
        for (int j = 0; j < 4; j++)
            #pragma unroll
            for (int r = 0; r < 4; r++) acc[i][j][r] = 0.f;

    const int a_lrow = lane & 15;
    const int a_lcol = (lane >> 4) << 3;
    const int bl_    = lane & 15;

    load_stage(0, 0);
    if (NC > 1) load_stage(1, 1);

    for (int kc = 0; kc < NC; kc++){
        if (kc + 1 < NC) cp_wait1(); else cp_wait0();
        __syncthreads();

        const uint32_t sa = sbase + (kc % NSTAGE) * STG_BYTES;
        const uint32_t sb = sa + 2*AH_BYTES;

        #pragma unroll
        for (int ks = 0; ks < 2; ks++){
            uint32_t ah[4][4], al_[4][4], bb[4][2];
            #pragma unroll
            for (int mt = 0; mt < 4; mt++){
                uint32_t ad = sa + 2 * ((wm*64 + mt*16 + a_lrow) * A_PAD + ks*16 + a_lcol);
                ldsm4(ah[mt],  ad);
                ldsm4(al_[mt], ad + AH_BYTES);
            }
            #pragma unroll
            for (int nt = 0; nt < 4; nt++){
                if (transB){
                    uint32_t bd = sb + 2 * ((ks*16 + bl_) * B_PAD_T + wn*32 + nt*8);
                    ldsm2t(bb[nt], bd);
                } else {
                    uint32_t bd = sb + 2 * ((wn*32 + nt*8 + (bl_ & 7)) * A_PAD + ks*16 + ((bl_ >> 3) << 3));
                    ldsm2(bb[nt], bd);
                }
            }
            #pragma unroll
            for (int mt = 0; mt < 4; mt++)
                #pragma unroll
                for (int nt = 0; nt < 4; nt++){
                    mma16816(acc[mt][nt], ah[mt],  bb[nt]);
                    mma16816(acc[mt][nt], al_[mt], bb[nt]);
                }
        }
        if (kc + 2 < NC) load_stage((kc + 2) % NSTAGE, kc + 2);
    }

    // ---- epilogue ----
    const int g = lane >> 2;
    const int t = lane & 3;
    #pragma unroll
    for (int mt = 0; mt < 4; mt++){
        int m = m0 + wm*64 + mt*16 + g;
        float bi_lo = bias ? bias[m]     : 0.f;
        float bi_hi = bias ? bias[m + 8] : 0.f;
        #pragma unroll
        for (int nt = 0; nt < 4; nt++){
            int nn = n0 + wn*32 + nt*8 + 2*t;
            float v00 = acc[mt][nt][0] * scale + bi_lo;
            float v01 = acc[mt][nt][1] * scale + bi_lo;
            float v10 = acc[mt][nt][2] * scale + bi_hi;
            float v11 = acc[mt][nt][3] * scale + bi_hi;
            size_t off0 = (size_t)b * yB + (size_t)m * yStride + nn;
            size_t off1 = off0 + (size_t)8 * yStride;
            if (epiMode == 1){
                float2 gp0 = *(const float2*)(Egp + off0);
                float2 gp1 = *(const float2*)(Egp + off1);
                float2 y0  = *(const float2*)(Ey  + off0);
                float2 y1  = *(const float2*)(Ey  + off1);
                float s0 = 1.f/(1.f+__expf(-gp0.x));
                float s1 = 1.f/(1.f+__expf(-gp0.y));
                float s2 = 1.f/(1.f+__expf(-gp1.x));
                float s3 = 1.f/(1.f+__expf(-gp1.y));
                float2 o0, o1;
                o0.x = y0.x + s0 * (v00 - y0.x);
                o0.y = y0.y + s1 * (v01 - y0.y);
                o1.x = y1.x + s2 * (v10 - y1.x);
                o1.y = y1.y + s3 * (v11 - y1.y);
                *(float2*)(Y + off0) = o0;
                *(float2*)(Y + off1) = o1;
            } else {
                if (Y){
                    float2 o0 = {v00, v01}, o1 = {v10, v11};
                    *(float2*)(Y + off0) = o0;
                    *(float2*)(Y + off1) = o1;
                }
                if (Yh && m >= yhOff){
                    size_t so0 = (size_t)b * yhB + (size_t)(m - yhOff) * N_ + nn;
                    size_t so1 = so0 + (size_t)8 * N_;
                    *(uint32_t*)(Yh + so0) = pack_h2(v00, v01);
                    *(uint32_t*)(Yh + so1) = pack_h2(v10, v11);
                }
            }
        }
    }
}

// ---------------------------------------------------------------------------
__global__ void split_w(const float* __restrict__ s,
                        __half* __restrict__ h, __half* __restrict__ l, int n)
{
    int i = blockIdx.x * 256 + threadIdx.x;
    if (i < n){
        float v = s[i];
        __half hh = __float2half_rn(v);
        h[i] = hh;
        l[i] = __float2half_rn(v - __half2float(hh));
    }
}
__global__ void conv_h(const float* __restrict__ s, __half* __restrict__ h, int n)
{
    int i = blockIdx.x * 256 + threadIdx.x;
    if (i < n) h[i] = __float2half_rn(s[i]);
}

// ---------------------------------------------------------------------------
__global__ void softmax_q(const float* __restrict__ qkv,
                          const float* __restrict__ mqk,
                          __half* __restrict__ qh_h, __half* __restrict__ qh_l)
{
    __shared__ float red[8];
    __shared__ float bc;
    const int row = blockIdx.x;
    const int b = row >> 9, c = row & 511;
    const float* q  = qkv + ((size_t)b*1536 + c) * (size_t)N_;
    const float* mq = mqk + ((size_t)b*1024 + c) * (size_t)N_;
    const size_t base = (size_t)row * N_;

    float v[16];
    float mx = -1e30f;
    #pragma unroll
    for (int i = 0; i < 16; i++){
        int idx = threadIdx.x + (i << 8);
        float tv = -fmaxf(q[idx] * mq[idx], 0.f);
        v[i] = tv;
        mx = fmaxf(mx, tv);
    }
    #pragma unroll
    for (int off = 16; off; off >>= 1)
        mx = fmaxf(mx, __shfl_xor_sync(0xffffffffu, mx, off));
    if ((threadIdx.x & 31) == 0) red[threadIdx.x >> 5] = mx;
    __syncthreads();
    if (threadIdx.x == 0){
        float tv = red[0];
        #pragma unroll
        for (int i = 1; i < 8; i++) tv = fmaxf(tv, red[i]);
        bc = tv;
    }
    __syncthreads();
    mx = bc;

    float sm = 0.f;
    #pragma unroll
    for (int i = 0; i < 16; i++){
        v[i] = __expf(v[i] - mx);
        sm += v[i];
    }
    #pragma unroll
    for (int off = 16; off; off >>= 1)
        sm += __shfl_xor_sync(0xffffffffu, sm, off);
    __syncthreads();
    if ((threadIdx.x & 31) == 0) red[threadIdx.x >> 5] = sm;
    __syncthreads();
    if (threadIdx.x == 0){
        float tv = 0.f;
        #pragma unroll
        for (int i = 0; i < 8; i++) tv += red[i];
        bc = tv;
    }
    __syncthreads();
    const float rinv = 1.f / bc;
    #pragma unroll
    for (int i = 0; i < 16; i++){
        int idx = threadIdx.x + (i << 8);
        float f = v[i] * rinv;
        __half h = __float2half_rn(f);
        qh_h[base + idx] = h;
        qh_l[base + idx] = __float2half_rn(f - __half2float(h));
    }
}

// ---------------------------------------------------------------------------
__global__ void relu_k(const float* __restrict__ qkv,
                       const float* __restrict__ mqk,
                       __half* __restrict__ kh)
{
    const int row = blockIdx.x;
    const int b = row >> 9, c = row & 511;
    const float4* k4 = (const float4*)(qkv + ((size_t)b*1536 + 512 + c) * (size_t)N_);
    const float4* m4 = (const float4*)(mqk + ((size_t)b*1024 + 512 + c) * (size_t)N_);
    uint32_t* oh = (uint32_t*)(kh + (size_t)row * N_);
    for (int i = threadIdx.x; i < N_/4; i += 256){
        float4 a = k4[i], m = m4[i];
        float r0 = fmaxf(a.x * m.x, 0.f);
        float r1 = fmaxf(a.y * m.y, 0.f);
        float r2 = fmaxf(a.z * m.z, 0.f);
        float r3 = fmaxf(a.w * m.w, 0.f);
        oh[2*i]   = pack_h2(r0, r1);
        oh[2*i+1] = pack_h2(r2, r3);
    }
}

// ---------------------------------------------------------------------------
__global__ void softmax_attn(float* __restrict__ S,
                             __half* __restrict__ ah, __half* __restrict__ al)
{
    __shared__ float red[4];
    __shared__ float bc;
    const int row = blockIdx.x;
    float* p = S + (size_t)row * 512;
    const size_t base = (size_t)row * 512;

    float v[4];
    float mx = -1e30f;
    #pragma unroll
    for (int i = 0; i < 4; i++){
        int idx = threadIdx.x + (i << 7);
        v[i] = p[idx];
        mx = fmaxf(mx, v[i]);
    }
    #pragma unroll
    for (int off = 16; off; off >>= 1)
        mx = fmaxf(mx, __shfl_xor_sync(0xffffffffu, mx, off));
    if ((threadIdx.x & 31) == 0) red[threadIdx.x >> 5] = mx;
    __syncthreads();
    if (threadIdx.x == 0)
        bc = fmaxf(fmaxf(red[0], red[1]), fmaxf(red[2], red[3]));
    __syncthreads();
    mx = bc;

    float sm = 0.f;
    #pragma unroll
    for (int i = 0; i < 4; i++){
        v[i] = __expf(v[i] - mx);
        sm += v[i];
    }
    #pragma unroll
    for (int off = 16; off; off >>= 1)
        sm += __shfl_xor_sync(0xffffffffu, sm, off);
    __syncthreads();
    if ((threadIdx.x & 31) == 0) red[threadIdx.x >> 5] = sm;
    __syncthreads();
    if (threadIdx.x == 0) bc = red[0] + red[1] + red[2] + red[3];
    __syncthreads();
    const float rinv = 1.f / bc;
    #pragma unroll
    for (int i = 0; i < 4; i++){
        int idx = threadIdx.x + (i << 7);
        float f = v[i] * rinv;
        p[idx] = f;
        __half h = __float2half_rn(f);
        ah[base + idx] = h;
        al[base + idx] = __float2half_rn(f - __half2float(h));
    }
}

// ---------------------------------------------------------------------------
extern "C" void kernel_launch(void* const* d_in, const int* in_sizes, int n_in,
                              void* d_out, int out_size)
{
    const float* x    = (const float*)d_in[0];
    const float* Wqkv = (const float*)d_in[1];
    const float* bqkv = (const float*)d_in[2];
    const float* Wm   = (const float*)d_in[3];
    const float* bm   = (const float*)d_in[4];
    const float* Wg   = (const float*)d_in[5];
    const float* bg   = (const float*)d_in[6];
    const float* Wr   = (const float*)d_in[7];
    const float* br   = (const float*)d_in[8];

    float* out  = (float*)d_out;
    float* attn = out + (size_t)B_ * C_ * N_;

    cudaFuncSetAttribute(mma_gemm, cudaFuncAttributeMaxDynamicSharedMemorySize, SMEM_TOTAL);

    float *p_qkv, *p_mqk, *p_y, *p_gp;
    __half *xh, *vh, *kh, *yh;
    __half *p_qh_h, *p_qh_l, *p_at_h, *p_at_l;
    __half *wqkv_h, *wqkv_l, *wm_h, *wm_l, *wg_h, *wg_l, *wr_h, *wr_l;
    cudaGetSymbolAddress((void**)&p_qkv, g_qkv);
    cudaGetSymbolAddress((void**)&p_mqk, g_mqk);
    cudaGetSymbolAddress((void**)&p_y,   g_y);
    cudaGetSymbolAddress((void**)&p_gp,  g_gp);
    cudaGetSymbolAddress((void**)&xh,  g_xh);
    cudaGetSymbolAddress((void**)&vh,  g_vh);
    cudaGetSymbolAddress((void**)&kh,  g_khh);
    cudaGetSymbolAddress((void**)&yh,  g_yh);
    cudaGetSymbolAddress((void**)&p_qh_h, g_qh_h);
    cudaGetSymbolAddress((void**)&p_qh_l, g_qh_l);
    cudaGetSymbolAddress((void**)&p_at_h, g_at_h);
    cudaGetSymbolAddress((void**)&p_at_l, g_at_l);
    cudaGetSymbolAddress((void**)&wqkv_h, g_wqkv_h);
    cudaGetSymbolAddress((void**)&wqkv_l, g_wqkv_l);
    cudaGetSymbolAddress((void**)&wm_h,   g_wm_h);
    cudaGetSymbolAddress((void**)&wm_l,   g_wm_l);
    cudaGetSymbolAddress((void**)&wg_h,   g_wg_h);
    cudaGetSymbolAddress((void**)&wg_l,   g_wg_l);
    cudaGetSymbolAddress((void**)&wr_h,   g_wr_h);
    cudaGetSymbolAddress((void**)&wr_l,   g_wr_l);

    const size_t sBCN = (size_t)C_ * N_;
    const size_t s3CN = (size_t)3*C_ * N_;
    const size_t s2CN = (size_t)2*C_ * N_;

    // 0) split weights (A operands), convert x (B operand)
    split_w<<<(3*C_*C_ + 255)/256, 256>>>(Wqkv, wqkv_h, wqkv_l, 3*C_*C_);
    split_w<<<(2*C_*C_ + 255)/256, 256>>>(Wm,   wm_h,   wm_l,   2*C_*C_);
    split_w<<<(2*C_*C_ + 255)/256, 256>>>(Wg,   wg_h,   wg_l,   2*C_*C_);
    split_w<<<(  C_*C_ + 255)/256, 256>>>(Wr,   wr_h,   wr_l,     C_*C_);
    conv_h<<<((int)(B_*sBCN) + 255)/256, 256>>>(x, xh, (int)(B_*sBCN));

    // 1) qkv = Wqkv @ x + bqkv ; emit v (rows >= 2C) fp16
    mma_gemm<<<dim3(N_/TN, 3*C_/TM, B_), 256, SMEM_TOTAL>>>(
        wqkv_h, wqkv_l, C_, 0,
        xh, sBCN, nullptr, 0, C_,
        bqkv, 1.f, p_qkv, s3CN, N_,
        vh, sBCN, 2*C_,
        nullptr, nullptr, 0, C_, 1);

    // 2) mqk = Wm @ v + bm
    mma_gemm<<<dim3(N_/TN, 2*C_/TM, B_), 256, SMEM_TOTAL>>>(
        wm_h, wm_l, C_, 0,
        vh, sBCN, nullptr, 0, C_,
        bm, 1.f, p_mqk, s2CN, N_,
        nullptr, 0, 0,
        nullptr, nullptr, 0, C_, 1);

    // 3) _q softmax -> fp16 hi/lo (A of scores)
    softmax_q<<<NROWS, 256>>>(p_qkv, p_mqk, p_qh_h, p_qh_l);

    // 4) _k = relu(k*mk) -> fp16 (B of scores)
    relu_k<<<NROWS, 256>>>(p_qkv, p_mqk, kh);

    // 5) scores = _q @ _k^T / sqrt(C)   (NT, K=4096)
    mma_gemm<<<dim3(C_/TN, C_/TM, B_), 256, SMEM_TOTAL>>>(
        p_qh_h, p_qh_l, N_, sBCN,
        kh, sBCN, nullptr, 0, N_,
        nullptr, 1.0f/sqrtf((float)C_), attn, (size_t)C_*C_, C_,
        nullptr, 0, 0,
        nullptr, nullptr, 0, N_, 0);

    // 6) attn = softmax(scores) in-place + fp16 hi/lo (A of y GEMM)
    softmax_attn<<<NROWS, 128>>>(attn, p_at_h, p_at_l);

    // 7) y = attn @ v ; fp32 y + fp16 yh
    mma_gemm<<<dim3(N_/TN, C_/TM, B_), 256, SMEM_TOTAL>>>(
        p_at_h, p_at_l, C_, (size_t)C_*C_,
        vh, sBCN, nullptr, 0, C_,
        nullptr, 1.f, p_y, sBCN, N_,
        yh, sBCN, 0,
        nullptr, nullptr, 0, C_, 1);

    // 8) gpre = Wg @ [y; x] + bg   (K=1024, two B sources)
    mma_gemm<<<dim3(N_/TN, C_/TM, B_), 256, SMEM_TOTAL>>>(
        wg_h, wg_l, 2*C_, 0,
        yh, sBCN, xh, sBCN, C_,
        bg, 1.f, p_gp, sBCN, N_,
        nullptr, 0, 0,
        nullptr, nullptr, 0, 2*C_, 1);

    // 9) r = Wr @ x + br fused: out = y + sigmoid(gp)*(r - y)
    mma_gemm<<<dim3(N_/TN, C_/TM, B_), 256, SMEM_TOTAL>>>(
        wr_h, wr_l, C_, 0,
        xh, sBCN, nullptr, 0, C_,
        br, 1.f, out, sBCN, N_,
        nullptr, 0, 0,
        p_gp, p_y, 1, C_, 1);
}

// round 7
// speedup vs baseline: 5.9769x; 1.4790x over previous
#include <cuda_runtime.h>
#include <cuda_fp16.h>
#include <math.h>
#include <stdint.h>
#include <stddef.h>

#define B_ 16
#define C_ 512
#define N_ 4096
#define NROWS (B_*C_)

// block tile
#define TM 128
#define TN 128
#define TKC 32

// smem layout (halves = fp16)
#define A_PAD 40
#define B_PAD_T 136
#define AH_BYTES 10240                    // 128*40*2
#define STG_BYTES (2*AH_BYTES)            // A + B = 20480
#define NSTAGE 4
#define SMEM_TOTAL (NSTAGE*STG_BYTES)     // 81920

// ---------------- scratch (device globals) ----------------
__device__ float g_qkv[(size_t)B_*3*C_*N_];   // only q,k rows written fp32
__device__ float g_mqk[(size_t)B_*2*C_*N_];
__device__ float g_y  [(size_t)B_*C_*N_];
__device__ float g_gp [(size_t)B_*C_*N_];
__device__ __half g_xh [(size_t)B_*C_*N_];
__device__ __half g_vh [(size_t)B_*C_*N_];
__device__ __half g_kh [(size_t)B_*C_*N_];
__device__ __half g_yh [(size_t)B_*C_*N_];
__device__ __half g_qh [(size_t)B_*C_*N_];
__device__ __half g_at [(size_t)B_*C_*C_];
__device__ __half g_wqkv[3*C_*C_];
__device__ __half g_wm[2*C_*C_];
__device__ __half g_wg[C_*2*C_];
__device__ __half g_wr[C_*C_];

// ---------------- PTX helpers (portable) ----------------
__device__ __forceinline__ void cpa16(uint32_t dst, const void* src){
    asm volatile("cp.async.cg.shared.global [%0], [%1], 16;"
                 :: "r"(dst), "l"(src) : "memory");
}
__device__ __forceinline__ void cp_commit(){
    asm volatile("cp.async.commit_group;" ::: "memory");
}
__device__ __forceinline__ void cp_wait2(){
    asm volatile("cp.async.wait_group 2;" ::: "memory");
}
__device__ __forceinline__ void cp_wait1(){
    asm volatile("cp.async.wait_group 1;" ::: "memory");
}
__device__ __forceinline__ void cp_wait0(){
    asm volatile("cp.async.wait_group 0;" ::: "memory");
}
__device__ __forceinline__ uint32_t smem_u32(const void* p){
    uint32_t a;
    asm("{ .reg .u64 t; cvta.to.shared.u64 t, %1; cvt.u32.u64 %0, t; }"
        : "=r"(a) : "l"(p));
    return a;
}
__device__ __forceinline__ void ldsm4(uint32_t* r, uint32_t addr){
    asm volatile("ldmatrix.sync.aligned.m8n8.x4.shared.b16 {%0,%1,%2,%3}, [%4];"
        : "=r"(r[0]), "=r"(r[1]), "=r"(r[2]), "=r"(r[3]) : "r"(addr));
}
__device__ __forceinline__ void ldsm2(uint32_t* r, uint32_t addr){
    asm volatile("ldmatrix.sync.aligned.m8n8.x2.shared.b16 {%0,%1}, [%2];"
        : "=r"(r[0]), "=r"(r[1]) : "r"(addr));
}
__device__ __forceinline__ void ldsm2t(uint32_t* r, uint32_t addr){
    asm volatile("ldmatrix.sync.aligned.m8n8.x2.trans.shared.b16 {%0,%1}, [%2];"
        : "=r"(r[0]), "=r"(r[1]) : "r"(addr));
}
__device__ __forceinline__ void mma16816(float* c, const uint32_t* a, const uint32_t* b){
    asm volatile(
        "mma.sync.aligned.m16n8k16.row.col.f32.f16.f16.f32 "
        "{%0,%1,%2,%3}, {%4,%5,%6,%7}, {%8,%9}, {%0,%1,%2,%3};"
        : "+f"(c[0]), "+f"(c[1]), "+f"(c[2]), "+f"(c[3])
        : "r"(a[0]), "r"(a[1]), "r"(a[2]), "r"(a[3]), "r"(b[0]), "r"(b[1]));
}
__device__ __forceinline__ uint32_t pack_h2(float x, float y){
    __half2 p(__float2half_rn(x), __float2half_rn(y));
    return *(uint32_t*)&p;
}

// ---------------------------------------------------------------------------
// Pure fp16 GEMM on mma.sync + 4-stage cp.async pipeline.
//   val = scale * sum_k A[m,k] * B[k,n] + bias[m]
// A: fp16 row-major (lda, aBatch).
// B: fp16. transB=1: MN-major rows k (stride N_); rows >= K1 from B2.
//    transB=0: K-major rows n (stride N_)  (NT GEMM).
// Outputs: fp32 Y for rows m < y32Max; fp16 Yh for rows >= yhOff.
// epiMode 1: out = Ey + sigmoid(Egp) * (val - Ey)
// ---------------------------------------------------------------------------
__global__ void __launch_bounds__(256, 2) mma_gemm(
    const __half* __restrict__ Ah, int lda, size_t aBatch,
    const __half* __restrict__ B1, size_t b1B,
    const __half* __restrict__ B2, size_t b2B, int K1,
    const float* __restrict__ bias, float scale,
    float* __restrict__ Y, size_t yB, int yStride, int y32Max,
    __half* __restrict__ Yh, size_t yhB, int yhOff,
    const float* __restrict__ Egp, const float* __restrict__ Ey, int epiMode,
    int K, int transB)
{
    extern __shared__ char smem[];
    const uint32_t sbase = smem_u32(smem);

    const int tid  = threadIdx.x;
    const int lane = tid & 31;
    const int wid  = tid >> 5;
    const int wm   = wid & 1;
    const int wn   = wid >> 1;
    const int b    = blockIdx.z;
    const int m0   = blockIdx.y * TM;
    const int n0   = blockIdx.x * TN;

    const __half* Ab = Ah + (size_t)b * aBatch;
    const int NC = K / TKC;

    auto load_stage = [&](int s, int kc){
        const uint32_t sa = sbase + s * STG_BYTES;
        #pragma unroll
        for (int it = 0; it < 2; it++){
            int slot = it * 256 + tid;
            int row = slot >> 2, c8 = (slot & 3) << 3;
            size_t go = (size_t)(m0 + row) * lda + kc * TKC + c8;
            cpa16(sa + 2 * (row * A_PAD + c8), Ab + go);
        }
        const uint32_t sb = sa + AH_BYTES;
        if (transB){
            #pragma unroll
            for (int it = 0; it < 2; it++){
                int slot = it * 256 + tid;
                int k = slot >> 4, n8 = (slot & 15) << 3;
                int kg = kc * TKC + k;
                const __half* src = (kg < K1)
                    ? (B1 + (size_t)b * b1B + (size_t)kg * N_ + n0 + n8)
                    : (B2 + (size_t)b * b2B + (size_t)(kg - K1) * N_ + n0 + n8);
                cpa16(sb + 2 * (k * B_PAD_T + n8), src);
            }
        } else {
            #pragma unroll
            for (int it = 0; it < 2; it++){
                int slot = it * 256 + tid;
                int n = slot >> 2, k8 = (slot & 3) << 3;
                size_t go = (size_t)b * b1B + (size_t)(n0 + n) * N_ + kc * TKC + k8;
                cpa16(sb + 2 * (n * A_PAD + k8), B1 + go);
            }
        }
        cp_commit();
    };

    float acc[4][4][4];
    #pragma unroll
    for (int i = 0; i < 4; i++)
        #pragma unroll
        for (int j = 0; j < 4; j++)
            #pragma unroll
            for (int r = 0; r < 4; r++) acc[i][j][r] = 0.f;

    const int a_lrow = lane & 15;
    const int a_lcol = (lane >> 4) << 3;
    const int bl_    = lane & 15;

    load_stage(0, 0);
    if (NC > 1) load_stage(1, 1);
    if (NC > 2) load_stage(2, 2);

    for (int kc = 0; kc < NC; kc++){
        // pending groups cover kc .. min(kc+2, NC-1); wait so kc is complete
        int pend = (NC - kc > 3) ? 3 : (NC - kc);
        if (pend == 3) cp_wait2();
        else if (pend == 2) cp_wait1();
        else cp_wait0();
        __syncthreads();

        const uint32_t sa = sbase + (kc % NSTAGE) * STG_BYTES;
        const uint32_t sb = sa + AH_BYTES;

        #pragma unroll
        for (int ks = 0; ks < 2; ks++){
            uint32_t ah[4][4], bb[4][2];
            #pragma unroll
            for (int mt = 0; mt < 4; mt++){
                uint32_t ad = sa + 2 * ((wm*64 + mt*16 + a_lrow) * A_PAD + ks*16 + a_lcol);
                ldsm4(ah[mt], ad);
            }
            #pragma unroll
            for (int nt = 0; nt < 4; nt++){
                if (transB){
                    uint32_t bd = sb + 2 * ((ks*16 + bl_) * B_PAD_T + wn*32 + nt*8);
                    ldsm2t(bb[nt], bd);
                } else {
                    uint32_t bd = sb + 2 * ((wn*32 + nt*8 + (bl_ & 7)) * A_PAD + ks*16 + ((bl_ >> 3) << 3));
                    ldsm2(bb[nt], bd);
                }
            }
            #pragma unroll
            for (int mt = 0; mt < 4; mt++)
                #pragma unroll
                for (int nt = 0; nt < 4; nt++)
                    mma16816(acc[mt][nt], ah[mt], bb[nt]);
        }
        if (kc + 3 < NC) load_stage((kc + 3) % NSTAGE, kc + 3);
    }

    // ---- epilogue ----
    const int g = lane >> 2;
    const int t = lane & 3;
    #pragma unroll
    for (int mt = 0; mt < 4; mt++){
        int m = m0 + wm*64 + mt*16 + g;
        float bi_lo = bias ? bias[m]     : 0.f;
        float bi_hi = bias ? bias[m + 8] : 0.f;
        #pragma unroll
        for (int nt = 0; nt < 4; nt++){
            int nn = n0 + wn*32 + nt*8 + 2*t;
            float v00 = acc[mt][nt][0] * scale + bi_lo;
            float v01 = acc[mt][nt][1] * scale + bi_lo;
            float v10 = acc[mt][nt][2] * scale + bi_hi;
            float v11 = acc[mt][nt][3] * scale + bi_hi;
            size_t off0 = (size_t)b * yB + (size_t)m * yStride + nn;
            size_t off1 = off0 + (size_t)8 * yStride;
            if (epiMode == 1){
                float2 gp0 = *(const float2*)(Egp + off0);
                float2 gp1 = *(const float2*)(Egp + off1);
                float2 y0  = *(const float2*)(Ey  + off0);
                float2 y1  = *(const float2*)(Ey  + off1);
                float s0 = 1.f/(1.f+__expf(-gp0.x));
                float s1 = 1.f/(1.f+__expf(-gp0.y));
                float s2 = 1.f/(1.f+__expf(-gp1.x));
                float s3 = 1.f/(1.f+__expf(-gp1.y));
                float2 o0, o1;
                o0.x = y0.x + s0 * (v00 - y0.x);
                o0.y = y0.y + s1 * (v01 - y0.y);
                o1.x = y1.x + s2 * (v10 - y1.x);
                o1.y = y1.y + s3 * (v11 - y1.y);
                *(float2*)(Y + off0) = o0;
                *(float2*)(Y + off1) = o1;
            } else {
                if (Y && m < y32Max){
                    float2 o0 = {v00, v01}, o1 = {v10, v11};
                    *(float2*)(Y + off0) = o0;
                    *(float2*)(Y + off1) = o1;
                }
                if (Yh && m >= yhOff){
                    size_t so0 = (size_t)b * yhB + (size_t)(m - yhOff) * N_ + nn;
                    size_t so1 = so0 + (size_t)8 * N_;
                    *(uint32_t*)(Yh + so0) = pack_h2(v00, v01);
                    *(uint32_t*)(Yh + so1) = pack_h2(v10, v11);
                }
            }
        }
    }
}

// ---------------------------------------------------------------------------
__global__ void conv_h(const float* __restrict__ s, __half* __restrict__ h, int n)
{
    int i = blockIdx.x * 256 + threadIdx.x;
    if (i < n) h[i] = __float2half_rn(s[i]);
}

// ---------------------------------------------------------------------------
__global__ void softmax_q(const float* __restrict__ qkv,
                          const float* __restrict__ mqk,
                          __half* __restrict__ qh)
{
    __shared__ float red[8];
    __shared__ float bc;
    const int row = blockIdx.x;
    const int b = row >> 9, c = row & 511;
    const float* q  = qkv + ((size_t)b*1536 + c) * (size_t)N_;
    const float* mq = mqk + ((size_t)b*1024 + c) * (size_t)N_;
    const size_t base = (size_t)row * N_;

    float v[16];
    float mx = -1e30f;
    #pragma unroll
    for (int i = 0; i < 16; i++){
        int idx = threadIdx.x + (i << 8);
        float tv = -fmaxf(q[idx] * mq[idx], 0.f);
        v[i] = tv;
        mx = fmaxf(mx, tv);
    }
    #pragma unroll
    for (int off = 16; off; off >>= 1)
        mx = fmaxf(mx, __shfl_xor_sync(0xffffffffu, mx, off));
    if ((threadIdx.x & 31) == 0) red[threadIdx.x >> 5] = mx;
    __syncthreads();
    if (threadIdx.x == 0){
        float tv = red[0];
        #pragma unroll
        for (int i = 1; i < 8; i++) tv = fmaxf(tv, red[i]);
        bc = tv;
    }
    __syncthreads();
    mx = bc;

    float sm = 0.f;
    #pragma unroll
    for (int i = 0; i < 16; i++){
        v[i] = __expf(v[i] - mx);
        sm += v[i];
    }
    #pragma unroll
    for (int off = 16; off; off >>= 1)
        sm += __shfl_xor_sync(0xffffffffu, sm, off);
    __syncthreads();
    if ((threadIdx.x & 31) == 0) red[threadIdx.x >> 5] = sm;
    __syncthreads();
    if (threadIdx.x == 0){
        float tv = 0.f;
        #pragma unroll
        for (int i = 0; i < 8; i++) tv += red[i];
        bc = tv;
    }
    __syncthreads();
    const float rinv = 1.f / bc;
    #pragma unroll
    for (int i = 0; i < 16; i++){
        int idx = threadIdx.x + (i << 8);
        qh[base + idx] = __float2half_rn(v[i] * rinv);
    }
}

// ---------------------------------------------------------------------------
__global__ void relu_k(const float* __restrict__ qkv,
                       const float* __restrict__ mqk,
                       __half* __restrict__ kh)
{
    const int row = blockIdx.x;
    const int b = row >> 9, c = row & 511;
    const float4* k4 = (const float4*)(qkv + ((size_t)b*1536 + 512 + c) * (size_t)N_);
    const float4* m4 = (const float4*)(mqk + ((size_t)b*1024 + 512 + c) * (size_t)N_);
    uint32_t* oh = (uint32_t*)(kh + (size_t)row * N_);
    for (int i = threadIdx.x; i < N_/4; i += 256){
        float4 a = k4[i], m = m4[i];
        oh[2*i]   = pack_h2(fmaxf(a.x*m.x, 0.f), fmaxf(a.y*m.y, 0.f));
        oh[2*i+1] = pack_h2(fmaxf(a.z*m.z, 0.f), fmaxf(a.w*m.w, 0.f));
    }
}

// ---------------------------------------------------------------------------
__global__ void softmax_attn(float* __restrict__ S, __half* __restrict__ ah)
{
    __shared__ float red[4];
    __shared__ float bc;
    const int row = blockIdx.x;
    float* p = S + (size_t)row * 512;
    const size_t base = (size_t)row * 512;

    float v[4];
    float mx = -1e30f;
    #pragma unroll
    for (int i = 0; i < 4; i++){
        int idx = threadIdx.x + (i << 7);
        v[i] = p[idx];
        mx = fmaxf(mx, v[i]);
    }
    #pragma unroll
    for (int off = 16; off; off >>= 1)
        mx = fmaxf(mx, __shfl_xor_sync(0xffffffffu, mx, off));
    if ((threadIdx.x & 31) == 0) red[threadIdx.x >> 5] = mx;
    __syncthreads();
    if (threadIdx.x == 0)
        bc = fmaxf(fmaxf(red[0], red[1]), fmaxf(red[2], red[3]));
    __syncthreads();
    mx = bc;

    float sm = 0.f;
    #pragma unroll
    for (int i = 0; i < 4; i++){
        v[i] = __expf(v[i] - mx);
        sm += v[i];
    }
    #pragma unroll
    for (int off = 16; off; off >>= 1)
        sm += __shfl_xor_sync(0xffffffffu, sm, off);
    __syncthreads();
    if ((threadIdx.x & 31) == 0) red[threadIdx.x >> 5] = sm;
    __syncthreads();
    if (threadIdx.x == 0) bc = red[0] + red[1] + red[2] + red[3];
    __syncthreads();
    const float rinv = 1.f / bc;
    #pragma unroll
    for (int i = 0; i < 4; i++){
        int idx = threadIdx.x + (i << 7);
        float f = v[i] * rinv;
        p[idx] = f;
        ah[base + idx] = __float2half_rn(f);
    }
}

// ---------------------------------------------------------------------------
extern "C" void kernel_launch(void* const* d_in, const int* in_sizes, int n_in,
                              void* d_out, int out_size)
{
    const float* x    = (const float*)d_in[0];
    const float* Wqkv = (const float*)d_in[1];
    const float* bqkv = (const float*)d_in[2];
    const float* Wm   = (const float*)d_in[3];
    const float* bm   = (const float*)d_in[4];
    const float* Wg   = (const float*)d_in[5];
    const float* bg   = (const float*)d_in[6];
    const float* Wr   = (const float*)d_in[7];
    const float* br   = (const float*)d_in[8];

    float* out  = (float*)d_out;
    float* attn = out + (size_t)B_ * C_ * N_;

    cudaFuncSetAttribute(mma_gemm, cudaFuncAttributeMaxDynamicSharedMemorySize, SMEM_TOTAL);

    float *p_qkv, *p_mqk, *p_y, *p_gp;
    __half *xh, *vh, *kh, *yh, *p_qh, *p_at;
    __half *wqkv, *wm, *wg, *wr;
    cudaGetSymbolAddress((void**)&p_qkv, g_qkv);
    cudaGetSymbolAddress((void**)&p_mqk, g_mqk);
    cudaGetSymbolAddress((void**)&p_y,   g_y);
    cudaGetSymbolAddress((void**)&p_gp,  g_gp);
    cudaGetSymbolAddress((void**)&xh,   g_xh);
    cudaGetSymbolAddress((void**)&vh,   g_vh);
    cudaGetSymbolAddress((void**)&kh,   g_kh);
    cudaGetSymbolAddress((void**)&yh,   g_yh);
    cudaGetSymbolAddress((void**)&p_qh, g_qh);
    cudaGetSymbolAddress((void**)&p_at, g_at);
    cudaGetSymbolAddress((void**)&wqkv, g_wqkv);
    cudaGetSymbolAddress((void**)&wm,   g_wm);
    cudaGetSymbolAddress((void**)&wg,   g_wg);
    cudaGetSymbolAddress((void**)&wr,   g_wr);

    const size_t sBCN = (size_t)C_ * N_;
    const size_t s3CN = (size_t)3*C_ * N_;
    const size_t s2CN = (size_t)2*C_ * N_;

    // 0) convert weights and x to fp16
    conv_h<<<(3*C_*C_ + 255)/256, 256>>>(Wqkv, wqkv, 3*C_*C_);
    conv_h<<<(2*C_*C_ + 255)/256, 256>>>(Wm,   wm,   2*C_*C_);
    conv_h<<<(2*C_*C_ + 255)/256, 256>>>(Wg,   wg,   2*C_*C_);
    conv_h<<<(  C_*C_ + 255)/256, 256>>>(Wr,   wr,     C_*C_);
    conv_h<<<((int)(B_*sBCN) + 255)/256, 256>>>(x, xh, (int)(B_*sBCN));

    // 1) qkv = Wqkv @ x + bqkv ; fp32 only q,k rows; v rows -> fp16 vh
    mma_gemm<<<dim3(N_/TN, 3*C_/TM, B_), 256, SMEM_TOTAL>>>(
        wqkv, C_, 0,
        xh, sBCN, nullptr, 0, C_,
        bqkv, 1.f, p_qkv, s3CN, N_, 2*C_,
        vh, sBCN, 2*C_,
        nullptr, nullptr, 0, C_, 1);

    // 2) mqk = Wm @ v + bm
    mma_gemm<<<dim3(N_/TN, 2*C_/TM, B_), 256, SMEM_TOTAL>>>(
        wm, C_, 0,
        vh, sBCN, nullptr, 0, C_,
        bm, 1.f, p_mqk, s2CN, N_, 2*C_,
        nullptr, 0, 0,
        nullptr, nullptr, 0, C_, 1);

    // 3) _q softmax -> fp16
    softmax_q<<<NROWS, 256>>>(p_qkv, p_mqk, p_qh);

    // 4) _k = relu(k*mk) -> fp16
    relu_k<<<NROWS, 256>>>(p_qkv, p_mqk, kh);

    // 5) scores = _q @ _k^T / sqrt(C)   (NT, K=4096)
    mma_gemm<<<dim3(C_/TN, C_/TM, B_), 256, SMEM_TOTAL>>>(
        p_qh, N_, sBCN,
        kh, sBCN, nullptr, 0, N_,
        nullptr, 1.0f/sqrtf((float)C_), attn, (size_t)C_*C_, C_, C_,
        nullptr, 0, 0,
        nullptr, nullptr, 0, N_, 0);

    // 6) attn = softmax(scores) in-place + fp16 copy
    softmax_attn<<<NROWS, 128>>>(attn, p_at);

    // 7) y = attn @ v ; fp32 y + fp16 yh
    mma_gemm<<<dim3(N_/TN, C_/TM, B_), 256, SMEM_TOTAL>>>(
        p_at, C_, (size_t)C_*C_,
        vh, sBCN, nullptr, 0, C_,
        nullptr, 1.f, p_y, sBCN, N_, C_,
        yh, sBCN, 0,
        nullptr, nullptr, 0, C_, 1);

    // 8) gpre = Wg @ [y; x] + bg   (K=1024, two B sources)
    mma_gemm<<<dim3(N_/TN, C_/TM, B_), 256, SMEM_TOTAL>>>(
        wg, 2*C_, 0,
        yh, sBCN, xh, sBCN, C_,
        bg, 1.f, p_gp, sBCN, N_, C_,
        nullptr, 0, 0,
        nullptr, nullptr, 0, 2*C_, 1);

    // 9) r = Wr @ x + br fused: out = y + sigmoid(gp)*(r - y)
    mma_gemm<<<dim3(N_/TN, C_/TM, B_), 256, SMEM_TOTAL>>>(
        wr, C_, 0,
        xh, sBCN, nullptr, 0, C_,
        br, 1.f, out, sBCN, N_, C_,
        nullptr, 0, 0,
        p_gp, p_y, 1, C_, 1);
}

// round 8
// speedup vs baseline: 6.4613x; 1.0810x over previous
#include <cuda_runtime.h>
#include <cuda_fp16.h>
#include <math.h>
#include <stdint.h>
#include <stddef.h>

#define B_ 16
#define C_ 512
#define N_ 4096
#define NROWS (B_*C_)

#define TM 128
#define TN 128
#define TKC 32

#define A_PAD 40
#define B_PAD_T 136
#define AH_BYTES 10240                    // 128*40*2
#define STG_BYTES (2*AH_BYTES)            // A + B = 20480
#define NSTAGE 4
#define SMEM_TOTAL (NSTAGE*STG_BYTES)     // 81920

// ---------------- scratch (device globals, all fp16) ----------------
__device__ __half g_qkvh[(size_t)B_*3*C_*N_];   // q,k,v fp16
__device__ __half g_s  [(size_t)B_*2*C_*N_];    // rows<C: -relu(q*mq); rows>=C: relu(k*mk)
__device__ __half g_qh [(size_t)B_*C_*N_];      // softmax result
__device__ __half g_yh [(size_t)B_*C_*N_];
__device__ __half g_gph[(size_t)B_*C_*N_];
__device__ __half g_at [(size_t)B_*C_*C_];
__device__ __half g_xh [(size_t)B_*C_*N_];
__device__ __half g_wqkv[3*C_*C_];
__device__ __half g_wm[2*C_*C_];
__device__ __half g_wg[C_*2*C_];
__device__ __half g_wr[C_*C_];

// ---------------- PTX helpers (portable) ----------------
__device__ __forceinline__ void cpa16(uint32_t dst, const void* src){
    asm volatile("cp.async.cg.shared.global [%0], [%1], 16;"
                 :: "r"(dst), "l"(src) : "memory");
}
__device__ __forceinline__ void cp_commit(){
    asm volatile("cp.async.commit_group;" ::: "memory");
}
__device__ __forceinline__ void cp_wait2(){
    asm volatile("cp.async.wait_group 2;" ::: "memory");
}
__device__ __forceinline__ void cp_wait1(){
    asm volatile("cp.async.wait_group 1;" ::: "memory");
}
__device__ __forceinline__ void cp_wait0(){
    asm volatile("cp.async.wait_group 0;" ::: "memory");
}
__device__ __forceinline__ uint32_t smem_u32(const void* p){
    uint32_t a;
    asm("{ .reg .u64 t; cvta.to.shared.u64 t, %1; cvt.u32.u64 %0, t; }"
        : "=r"(a) : "l"(p));
    return a;
}
__device__ __forceinline__ void ldsm4(uint32_t* r, uint32_t addr){
    asm volatile("ldmatrix.sync.aligned.m8n8.x4.shared.b16 {%0,%1,%2,%3}, [%4];"
        : "=r"(r[0]), "=r"(r[1]), "=r"(r[2]), "=r"(r[3]) : "r"(addr));
}
__device__ __forceinline__ void ldsm2(uint32_t* r, uint32_t addr){
    asm volatile("ldmatrix.sync.aligned.m8n8.x2.shared.b16 {%0,%1}, [%2];"
        : "=r"(r[0]), "=r"(r[1]) : "r"(addr));
}
__device__ __forceinline__ void ldsm2t(uint32_t* r, uint32_t addr){
    asm volatile("ldmatrix.sync.aligned.m8n8.x2.trans.shared.b16 {%0,%1}, [%2];"
        : "=r"(r[0]), "=r"(r[1]) : "r"(addr));
}
__device__ __forceinline__ void mma16816(float* c, const uint32_t* a, const uint32_t* b){
    asm volatile(
        "mma.sync.aligned.m16n8k16.row.col.f32.f16.f16.f32 "
        "{%0,%1,%2,%3}, {%4,%5,%6,%7}, {%8,%9}, {%0,%1,%2,%3};"
        : "+f"(c[0]), "+f"(c[1]), "+f"(c[2]), "+f"(c[3])
        : "r"(a[0]), "r"(a[1]), "r"(a[2]), "r"(a[3]), "r"(b[0]), "r"(b[1]));
}
__device__ __forceinline__ uint32_t pack_h2(float x, float y){
    __half2 p(__float2half_rn(x), __float2half_rn(y));
    return *(uint32_t*)&p;
}
__device__ __forceinline__ float2 unpack_h2(uint32_t u){
    __half2 p = *(__half2*)&u;
    return make_float2(__half2float(p.x), __half2float(p.y));
}

// ---------------------------------------------------------------------------
// Pure fp16 GEMM on mma.sync + 4-stage cp.async pipeline.
//   val = scale * sum_k A[m,k] * B[k,n] + bias[m]
// epiMode 0: fp32 Y rows m<y32Max; fp16 Yh rows >= yhOff.
// epiMode 1: Y(fp32) = Ey + sigmoid(Egp)*(val - Ey), Egp/Ey fp16.
// epiMode 2: prod = val * Eq[m,n];  Yh = (m<C_) ? -relu(prod) : relu(prod).
// ---------------------------------------------------------------------------
__global__ void __launch_bounds__(256, 2) mma_gemm(
    const __half* __restrict__ Ah, int lda, size_t aBatch,
    const __half* __restrict__ B1, size_t b1B,
    const __half* __restrict__ B2, size_t b2B, int K1,
    const float* __restrict__ bias, float scale,
    float* __restrict__ Y, size_t yB, int yStride, int y32Max,
    __half* __restrict__ Yh, size_t yhB, int yhOff,
    const __half* __restrict__ Egp, const __half* __restrict__ Ey,
    const __half* __restrict__ Eq, size_t eqB, int epiMode,
    int K, int transB)
{
    extern __shared__ char smem[];
    const uint32_t sbase = smem_u32(smem);

    const int tid  = threadIdx.x;
    const int lane = tid & 31;
    const int wid  = tid >> 5;
    const int wm   = wid & 1;
    const int wn   = wid >> 1;
    const int b    = blockIdx.z;
    const int m0   = blockIdx.y * TM;
    const int n0   = blockIdx.x * TN;

    const __half* Ab = Ah + (size_t)b * aBatch;
    const int NC = K / TKC;

    auto load_stage = [&](int s, int kc){
        const uint32_t sa = sbase + s * STG_BYTES;
        #pragma unroll
        for (int it = 0; it < 2; it++){
            int slot = it * 256 + tid;
            int row = slot >> 2, c8 = (slot & 3) << 3;
            size_t go = (size_t)(m0 + row) * lda + kc * TKC + c8;
            cpa16(sa + 2 * (row * A_PAD + c8), Ab + go);
        }
        const uint32_t sb = sa + AH_BYTES;
        if (transB){
            #pragma unroll
            for (int it = 0; it < 2; it++){
                int slot = it * 256 + tid;
                int k = slot >> 4, n8 = (slot & 15) << 3;
                int kg = kc * TKC + k;
                const __half* src = (kg < K1)
                    ? (B1 + (size_t)b * b1B + (size_t)kg * N_ + n0 + n8)
                    : (B2 + (size_t)b * b2B + (size_t)(kg - K1) * N_ + n0 + n8);
                cpa16(sb + 2 * (k * B_PAD_T + n8), src);
            }
        } else {
            #pragma unroll
            for (int it = 0; it < 2; it++){
                int slot = it * 256 + tid;
                int n = slot >> 2, k8 = (slot & 3) << 3;
                size_t go = (size_t)b * b1B + (size_t)(n0 + n) * N_ + kc * TKC + k8;
                cpa16(sb + 2 * (n * A_PAD + k8), B1 + go);
            }
        }
        cp_commit();
    };

    float acc[4][4][4];
    #pragma unroll
    for (int i = 0; i < 4; i++)
        #pragma unroll
        for (int j = 0; j < 4; j++)
            #pragma unroll
            for (int r = 0; r < 4; r++) acc[i][j][r] = 0.f;

    const int a_lrow = lane & 15;
    const int a_lcol = (lane >> 4) << 3;
    const int bl_    = lane & 15;

    load_stage(0, 0);
    if (NC > 1) load_stage(1, 1);
    if (NC > 2) load_stage(2, 2);

    for (int kc = 0; kc < NC; kc++){
        int pend = (NC - kc > 3) ? 3 : (NC - kc);
        if (pend == 3) cp_wait2();
        else if (pend == 2) cp_wait1();
        else cp_wait0();
        __syncthreads();

        const uint32_t sa = sbase + (kc % NSTAGE) * STG_BYTES;
        const uint32_t sb = sa + AH_BYTES;

        #pragma unroll
        for (int ks = 0; ks < 2; ks++){
            uint32_t ah[4][4], bb[4][2];
            #pragma unroll
            for (int mt = 0; mt < 4; mt++){
                uint32_t ad = sa + 2 * ((wm*64 + mt*16 + a_lrow) * A_PAD + ks*16 + a_lcol);
                ldsm4(ah[mt], ad);
            }
            #pragma unroll
            for (int nt = 0; nt < 4; nt++){
                if (transB){
                    uint32_t bd = sb + 2 * ((ks*16 + bl_) * B_PAD_T + wn*32 + nt*8);
                    ldsm2t(bb[nt], bd);
                } else {
                    uint32_t bd = sb + 2 * ((wn*32 + nt*8 + (bl_ & 7)) * A_PAD + ks*16 + ((bl_ >> 3) << 3));
                    ldsm2(bb[nt], bd);
                }
            }
            #pragma unroll
            for (int mt = 0; mt < 4; mt++)
                #pragma unroll
                for (int nt = 0; nt < 4; nt++)
                    mma16816(acc[mt][nt], ah[mt], bb[nt]);
        }
        if (kc + 3 < NC) load_stage((kc + 3) % NSTAGE, kc + 3);
    }

    // ---- epilogue ----
    const int g = lane >> 2;
    const int t = lane & 3;
    #pragma unroll
    for (int mt = 0; mt < 4; mt++){
        int m = m0 + wm*64 + mt*16 + g;
        float bi_lo = bias ? bias[m]     : 0.f;
        float bi_hi = bias ? bias[m + 8] : 0.f;
        #pragma unroll
        for (int nt = 0; nt < 4; nt++){
            int nn = n0 + wn*32 + nt*8 + 2*t;
            float v00 = acc[mt][nt][0] * scale + bi_lo;
            float v01 = acc[mt][nt][1] * scale + bi_lo;
            float v10 = acc[mt][nt][2] * scale + bi_hi;
            float v11 = acc[mt][nt][3] * scale + bi_hi;

            if (epiMode == 1){
                size_t eo0 = (size_t)b * yhB + (size_t)m * N_ + nn;
                size_t eo1 = eo0 + (size_t)8 * N_;
                float2 gp0 = unpack_h2(*(const uint32_t*)(Egp + eo0));
                float2 gp1 = unpack_h2(*(const uint32_t*)(Egp + eo1));
                float2 y0  = unpack_h2(*(const uint32_t*)(Ey + eo0));
                float2 y1  = unpack_h2(*(const uint32_t*)(Ey + eo1));
                float s0 = 1.f/(1.f+__expf(-gp0.x));
                float s1 = 1.f/(1.f+__expf(-gp0.y));
                float s2 = 1.f/(1.f+__expf(-gp1.x));
                float s3 = 1.f/(1.f+__expf(-gp1.y));
                size_t off0 = (size_t)b * yB + (size_t)m * yStride + nn;
                size_t off1 = off0 + (size_t)8 * yStride;
                float2 o0, o1;
                o0.x = y0.x + s0 * (v00 - y0.x);
                o0.y = y0.y + s1 * (v01 - y0.y);
                o1.x = y1.x + s2 * (v10 - y1.x);
                o1.y = y1.y + s3 * (v11 - y1.y);
                *(float2*)(Y + off0) = o0;
                *(float2*)(Y + off1) = o1;
            } else if (epiMode == 2){
                size_t qo0 = (size_t)b * eqB + (size_t)m * N_ + nn;
                size_t qo1 = qo0 + (size_t)8 * N_;
                float2 q0 = unpack_h2(*(const uint32_t*)(Eq + qo0));
                float2 q1 = unpack_h2(*(const uint32_t*)(Eq + qo1));
                float p00 = v00 * q0.x, p01 = v01 * q0.y;
                float p10 = v10 * q1.x, p11 = v11 * q1.y;
                bool neg0 = (m < C_), neg1 = (m + 8 < C_);
                p00 = neg0 ? -fmaxf(p00, 0.f) : fmaxf(p00, 0.f);
                p01 = neg0 ? -fmaxf(p01, 0.f) : fmaxf(p01, 0.f);
                p10 = neg1 ? -fmaxf(p10, 0.f) : fmaxf(p10, 0.f);
                p11 = neg1 ? -fmaxf(p11, 0.f) : fmaxf(p11, 0.f);
                size_t so0 = (size_t)b * yhB + (size_t)m * N_ + nn;
                size_t so1 = so0 + (size_t)8 * N_;
                *(uint32_t*)(Yh + so0) = pack_h2(p00, p01);
                *(uint32_t*)(Yh + so1) = pack_h2(p10, p11);
            } else {
                if (Y && m < y32Max){
                    size_t off0 = (size_t)b * yB + (size_t)m * yStride + nn;
                    size_t off1 = off0 + (size_t)8 * yStride;
                    float2 o0 = {v00, v01}, o1 = {v10, v11};
                    *(float2*)(Y + off0) = o0;
                    *(float2*)(Y + off1) = o1;
                }
                if (Yh && m >= yhOff){
                    size_t so0 = (size_t)b * yhB + (size_t)(m - yhOff) * N_ + nn;
                    size_t so1 = so0 + (size_t)8 * N_;
                    *(uint32_t*)(Yh + so0) = pack_h2(v00, v01);
                    *(uint32_t*)(Yh + so1) = pack_h2(v10, v11);
                }
            }
        }
    }
}

// ---------------------------------------------------------------------------
__global__ void conv_h(const float* __restrict__ s, __half* __restrict__ h, int n)
{
    int i = blockIdx.x * 256 + threadIdx.x;
    if (i < n) h[i] = __float2half_rn(s[i]);
}

// ---------------------------------------------------------------------------
// softmax over precomputed t = -relu(q*mq) fp16 rows (rows 0..C of g_s)
// ---------------------------------------------------------------------------
__global__ void softmax_q(const __half* __restrict__ tbuf, __half* __restrict__ qh)
{
    __shared__ float red[8];
    __shared__ float bc;
    const int row = blockIdx.x;
    const int b = row >> 9, c = row & 511;
    const uint32_t* src = (const uint32_t*)(tbuf + ((size_t)b*1024 + c) * (size_t)N_);
    uint32_t* dst = (uint32_t*)(qh + (size_t)row * N_);

    float v[16];
    float mx = -1e30f;
    #pragma unroll
    for (int i = 0; i < 8; i++){
        int idx = threadIdx.x + (i << 8);     // half2 index, 2048 total
        float2 f = unpack_h2(src[idx]);
        v[2*i]   = f.x;
        v[2*i+1] = f.y;
        mx = fmaxf(mx, fmaxf(f.x, f.y));
    }
    #pragma unroll
    for (int off = 16; off; off >>= 1)
        mx = fmaxf(mx, __shfl_xor_sync(0xffffffffu, mx, off));
    if ((threadIdx.x & 31) == 0) red[threadIdx.x >> 5] = mx;
    __syncthreads();
    if (threadIdx.x == 0){
        float tv = red[0];
        #pragma unroll
        for (int i = 1; i < 8; i++) tv = fmaxf(tv, red[i]);
        bc = tv;
    }
    __syncthreads();
    mx = bc;

    float sm = 0.f;
    #pragma unroll
    for (int i = 0; i < 16; i++){
        v[i] = __expf(v[i] - mx);
        sm += v[i];
    }
    #pragma unroll
    for (int off = 16; off; off >>= 1)
        sm += __shfl_xor_sync(0xffffffffu, sm, off);
    __syncthreads();
    if ((threadIdx.x & 31) == 0) red[threadIdx.x >> 5] = sm;
    __syncthreads();
    if (threadIdx.x == 0){
        float tv = 0.f;
        #pragma unroll
        for (int i = 0; i < 8; i++) tv += red[i];
        bc = tv;
    }
    __syncthreads();
    const float rinv = 1.f / bc;
    #pragma unroll
    for (int i = 0; i < 8; i++){
        int idx = threadIdx.x + (i << 8);
        dst[idx] = pack_h2(v[2*i] * rinv, v[2*i+1] * rinv);
    }
}

// ---------------------------------------------------------------------------
__global__ void softmax_attn(float* __restrict__ S, __half* __restrict__ ah)
{
    __shared__ float red[4];
    __shared__ float bc;
    const int row = blockIdx.x;
    float* p = S + (size_t)row * 512;
    const size_t base = (size_t)row * 512;

    float v[4];
    float mx = -1e30f;
    #pragma unroll
    for (int i = 0; i < 4; i++){
        int idx = threadIdx.x + (i << 7);
        v[i] = p[idx];
        mx = fmaxf(mx, v[i]);
    }
    #pragma unroll
    for (int off = 16; off; off >>= 1)
        mx = fmaxf(mx, __shfl_xor_sync(0xffffffffu, mx, off));
    if ((threadIdx.x & 31) == 0) red[threadIdx.x >> 5] = mx;
    __syncthreads();
    if (threadIdx.x == 0)
        bc = fmaxf(fmaxf(red[0], red[1]), fmaxf(red[2], red[3]));
    __syncthreads();
    mx = bc;

    float sm = 0.f;
    #pragma unroll
    for (int i = 0; i < 4; i++){
        v[i] = __expf(v[i] - mx);
        sm += v[i];
    }
    #pragma unroll
    for (int off = 16; off; off >>= 1)
        sm += __shfl_xor_sync(0xffffffffu, sm, off);
    __syncthreads();
    if ((threadIdx.x & 31) == 0) red[threadIdx.x >> 5] = sm;
    __syncthreads();
    if (threadIdx.x == 0) bc = red[0] + red[1] + red[2] + red[3];
    __syncthreads();
    const float rinv = 1.f / bc;
    #pragma unroll
    for (int i = 0; i < 4; i++){
        int idx = threadIdx.x + (i << 7);
        float f = v[i] * rinv;
        p[idx] = f;
        ah[base + idx] = __float2half_rn(f);
    }
}

// ---------------------------------------------------------------------------
extern "C" void kernel_launch(void* const* d_in, const int* in_sizes, int n_in,
                              void* d_out, int out_size)
{
    const float* x    = (const float*)d_in[0];
    const float* Wqkv = (const float*)d_in[1];
    const float* bqkv = (const float*)d_in[2];
    const float* Wm   = (const float*)d_in[3];
    const float* bm   = (const float*)d_in[4];
    const float* Wg   = (const float*)d_in[5];
    const float* bg   = (const float*)d_in[6];
    const float* Wr   = (const float*)d_in[7];
    const float* br   = (const float*)d_in[8];

    float* out  = (float*)d_out;
    float* attn = out + (size_t)B_ * C_ * N_;

    cudaFuncSetAttribute(mma_gemm, cudaFuncAttributeMaxDynamicSharedMemorySize, SMEM_TOTAL);

    __half *qkvh, *sbuf, *p_qh, *yh, *gph, *p_at, *xh;
    __half *wqkv, *wm, *wg, *wr;
    cudaGetSymbolAddress((void**)&qkvh, g_qkvh);
    cudaGetSymbolAddress((void**)&sbuf, g_s);
    cudaGetSymbolAddress((void**)&p_qh, g_qh);
    cudaGetSymbolAddress((void**)&yh,   g_yh);
    cudaGetSymbolAddress((void**)&gph,  g_gph);
    cudaGetSymbolAddress((void**)&p_at, g_at);
    cudaGetSymbolAddress((void**)&xh,   g_xh);
    cudaGetSymbolAddress((void**)&wqkv, g_wqkv);
    cudaGetSymbolAddress((void**)&wm,   g_wm);
    cudaGetSymbolAddress((void**)&wg,   g_wg);
    cudaGetSymbolAddress((void**)&wr,   g_wr);

    const size_t sBCN = (size_t)C_ * N_;
    const size_t s3CN = (size_t)3*C_ * N_;
    const size_t s2CN = (size_t)2*C_ * N_;

    // 0) convert weights and x to fp16
    conv_h<<<(3*C_*C_ + 255)/256, 256>>>(Wqkv, wqkv, 3*C_*C_);
    conv_h<<<(2*C_*C_ + 255)/256, 256>>>(Wm,   wm,   2*C_*C_);
    conv_h<<<(2*C_*C_ + 255)/256, 256>>>(Wg,   wg,   2*C_*C_);
    conv_h<<<(  C_*C_ + 255)/256, 256>>>(Wr,   wr,     C_*C_);
    conv_h<<<((int)(B_*sBCN) + 255)/256, 256>>>(x, xh, (int)(B_*sBCN));

    // 1) qkv = Wqkv @ x + bqkv  -> all fp16 (q,k,v)
    mma_gemm<<<dim3(N_/TN, 3*C_/TM, B_), 256, SMEM_TOTAL>>>(
        wqkv, C_, 0,
        xh, sBCN, nullptr, 0, C_,
        bqkv, 1.f, nullptr, 0, 0, 0,
        qkvh, s3CN, 0,
        nullptr, nullptr, nullptr, 0, 0, C_, 1);

    // 2) mqk = Wm @ v + bm ; epilogue 2: g_s = {-relu(q*mq) | relu(k*mk)} fp16
    mma_gemm<<<dim3(N_/TN, 2*C_/TM, B_), 256, SMEM_TOTAL>>>(
        wm, C_, 0,
        qkvh + (size_t)2*C_*N_, s3CN, nullptr, 0, C_,
        bm, 1.f, nullptr, 0, 0, 0,
        sbuf, s2CN, 0,
        nullptr, nullptr, qkvh, s3CN, 2, C_, 1);

    // 3) _q = softmax over g_s rows 0..C -> fp16 qh
    softmax_q<<<NROWS, 256>>>(sbuf, p_qh);

    // 4) scores = _q @ _k^T / sqrt(C)  (NT, K=4096); _k = g_s rows C..2C
    mma_gemm<<<dim3(C_/TN, C_/TM, B_), 256, SMEM_TOTAL>>>(
        p_qh, N_, sBCN,
        sbuf + (size_t)C_*N_, s2CN, nullptr, 0, N_,
        nullptr, 1.0f/sqrtf((float)C_), attn, (size_t)C_*C_, C_, C_,
        nullptr, 0, 0,
        nullptr, nullptr, nullptr, 0, 0, N_, 0);

    // 5) attn = softmax(scores) in-place + fp16 copy
    softmax_attn<<<NROWS, 128>>>(attn, p_at);

    // 6) y = attn @ v -> fp16 yh
    mma_gemm<<<dim3(N_/TN, C_/TM, B_), 256, SMEM_TOTAL>>>(
        p_at, C_, (size_t)C_*C_,
        qkvh + (size_t)2*C_*N_, s3CN, nullptr, 0, C_,
        nullptr, 1.f, nullptr, 0, 0, 0,
        yh, sBCN, 0,
        nullptr, nullptr, nullptr, 0, 0, C_, 1);

    // 7) gpre = Wg @ [y; x] + bg -> fp16 gph
    mma_gemm<<<dim3(N_/TN, C_/TM, B_), 256, SMEM_TOTAL>>>(
        wg, 2*C_, 0,
        yh, sBCN, xh, sBCN, C_,
        bg, 1.f, nullptr, 0, 0, 0,
        gph, sBCN, 0,
        nullptr, nullptr, nullptr, 0, 0, 2*C_, 1);

    // 8) r = Wr @ x + br ; out = y + sigmoid(gp)*(r - y)
    mma_gemm<<<dim3(N_/TN, C_/TM, B_), 256, SMEM_TOTAL>>>(
        wr, C_, 0,
        xh, sBCN, nullptr, 0, C_,
        br, 1.f, out, sBCN, N_, C_,
        nullptr, sBCN, 0,
        gph, yh, nullptr, 0, 1, C_, 1);
}